// round 12
// baseline (speedup 1.0000x reference)
#include <cuda_runtime.h>
#include <cuda_bf16.h>
#include <math.h>
#include <stdint.h>

// Problem constants (fixed instance)
constexpr int NP   = 1024;   // N == N_ (train/test points)
constexpr int LT   = 4;      // tasks
constexpr int RNK_MAX = 8;
constexpr int NTOT = 1152;   // RHS width: 1024 Cx cols + 1 ytilde col + pad to 9*128
constexpr int NKB  = 16;     // 1024 / 64 block steps

// Output offsets (fp32 elements)
constexpr size_t OFF_FMEAN = 0;
constexpr size_t OFF_FVAR  = 4096;
constexpr size_t OFF_NOISE = OFF_FVAR + (size_t)4096 * 4096;
constexpr size_t OFF_OUT4  = OFF_NOISE + (size_t)4096 * 4096;

// -------- device scratch (static, no allocation) --------
__device__ float g_A[LT * NP * NP];          // lambda_c*C + I, then Cholesky L (lower)
__device__ float g_B[LT * NP * NTOT];        // RHS -> forward-solved P_c (and w_c in col 1024)
__device__ float g_H[LT * NP * NTOT];        // H_c = P_c^T * P_c  (col 1024 = g_c)
__device__ float g_Cxx[NP * NP];             // rbf(test_X, test_X)
__device__ float g_Linv[LT * NKB * 64 * 64]; // per-step 64x64 diag-block inverses
__device__ __nv_bfloat16 g_Qh[LT * (size_t)NTOT * NP]; // Q = P^T, bf16 hi (filled by combo1)
__device__ __nv_bfloat16 g_Ql[LT * (size_t)NTOT * NP]; // Q residual, bf16 lo
__device__ __nv_bfloat16 g_Ph[LT * 960 * 64];          // current TRSM'd panel, bf16 hi
__device__ __nv_bfloat16 g_Pl[LT * 960 * 64];          // panel residual, bf16 lo
__device__ float g_lambda[LT];
__device__ float g_R[LT * LT];               // R = U^T Dn^{-1/2}
__device__ float g_M[LT * LT];               // M = R * T
__device__ float g_Tm[LT * LT];              // task_K
__device__ float g_noise[LT];                // exp(log_noise)

// -------- packed fp32x2 helpers --------
__device__ __forceinline__ unsigned long long f2pack(float lo, float hi)
{
    unsigned long long r;
    asm("mov.b64 %0, {%1, %2};" : "=l"(r) : "f"(lo), "f"(hi));
    return r;
}
__device__ __forceinline__ void f2unpack(unsigned long long v, float& lo, float& hi)
{
    asm("mov.b64 {%0, %1}, %2;" : "=f"(lo), "=f"(hi) : "l"(v));
}
__device__ __forceinline__ void f2fma(unsigned long long& d,
                                      unsigned long long a, unsigned long long b)
{
    asm("fma.rn.f32x2 %0, %1, %2, %3;" : "=l"(d) : "l"(a), "l"(b), "l"(d));
}

// -------- mma.sync / ldmatrix helpers (arch-portable tensor path) --------
__device__ __forceinline__ uint32_t smem_u32(const void* p)
{
    uint32_t a;
    asm("{ .reg .u64 t; cvta.to.shared.u64 t, %1; cvt.u32.u64 %0, t; }" : "=r"(a) : "l"(p));
    return a;
}
__device__ __forceinline__ void ldmx4(uint32_t* r, uint32_t addr)
{
    asm volatile("ldmatrix.sync.aligned.m8n8.x4.shared.b16 {%0,%1,%2,%3}, [%4];"
        : "=r"(r[0]), "=r"(r[1]), "=r"(r[2]), "=r"(r[3]) : "r"(addr));
}
__device__ __forceinline__ void mma16816(float* d, const uint32_t* a,
                                         uint32_t b0, uint32_t b1)
{
    asm volatile(
        "mma.sync.aligned.m16n8k16.row.col.f32.bf16.bf16.f32 "
        "{%0,%1,%2,%3}, {%4,%5,%6,%7}, {%8,%9}, {%0,%1,%2,%3};"
        : "+f"(d[0]), "+f"(d[1]), "+f"(d[2]), "+f"(d[3])
        : "r"(a[0]), "r"(a[1]), "r"(a[2]), "r"(a[3]), "r"(b0), "r"(b1));
}
__device__ __forceinline__ void bfsplit(float v, __nv_bfloat16& h, __nv_bfloat16& l)
{
    h = __float2bfloat16(v);
    l = __float2bfloat16(v - __bfloat162float(h));
}

// =====================================================================
// Small setup: task_K, 4x4 Jacobi eigendecomposition, R, M (fp32, 10 sweeps)
// =====================================================================
__global__ void k_setup(const float* __restrict__ cf,
                        const float* __restrict__ log_var,
                        const float* __restrict__ log_noise,
                        int rank)
{
    if (threadIdx.x != 0) return;
    float T[LT][LT], Tt[LT][LT], U[LT][LT], sv[LT];
#pragma unroll
    for (int a = 0; a < LT; a++) sv[a] = expf(-0.5f * log_noise[a]);
    for (int a = 0; a < LT; a++)
        for (int b = 0; b < LT; b++) {
            float s = 0.0f;
            for (int r = 0; r < rank && r < RNK_MAX; r++)
                s += cf[a * rank + r] * cf[b * rank + r];
            if (a == b) s += expf(log_var[a]);
            T[a][b] = s;
        }
#pragma unroll
    for (int a = 0; a < LT; a++)
#pragma unroll
        for (int b = 0; b < LT; b++) {
            Tt[a][b] = sv[a] * sv[b] * T[a][b];
            U[a][b] = (a == b) ? 1.0f : 0.0f;
        }
#pragma unroll 1
    for (int sweep = 0; sweep < 10; sweep++) {
#pragma unroll
        for (int p = 0; p < LT; p++)
#pragma unroll
            for (int q = p + 1; q < LT; q++) {
                float apq = Tt[p][q];
                if (fabsf(apq) < 1e-30f) continue;
                float tau = (Tt[q][q] - Tt[p][p]) / (2.0f * apq);
                float tt = ((tau >= 0.0f) ? 1.0f : -1.0f) / (fabsf(tau) + sqrtf(1.0f + tau * tau));
                float cc = rsqrtf(1.0f + tt * tt);
                float ss = tt * cc;
#pragma unroll
                for (int k = 0; k < LT; k++) {
                    float akp = Tt[k][p], akq = Tt[k][q];
                    Tt[k][p] = cc * akp - ss * akq;
                    Tt[k][q] = ss * akp + cc * akq;
                }
#pragma unroll
                for (int k = 0; k < LT; k++) {
                    float apk = Tt[p][k], aqk = Tt[q][k];
                    Tt[p][k] = cc * apk - ss * aqk;
                    Tt[q][k] = ss * apk + cc * aqk;
                }
#pragma unroll
                for (int k = 0; k < LT; k++) {
                    float ukp = U[k][p], ukq = U[k][q];
                    U[k][p] = cc * ukp - ss * ukq;
                    U[k][q] = ss * ukp + cc * ukq;
                }
            }
    }
    float R[LT][LT];
#pragma unroll
    for (int c = 0; c < LT; c++) {
        g_lambda[c] = Tt[c][c];
#pragma unroll
        for (int a = 0; a < LT; a++) {
            R[c][a] = U[a][c] * sv[a];
            g_R[c * LT + a] = R[c][a];
        }
    }
#pragma unroll
    for (int c = 0; c < LT; c++)
#pragma unroll
        for (int b = 0; b < LT; b++) {
            float m = 0.0f;
#pragma unroll
            for (int a = 0; a < LT; a++) m += R[c][a] * T[a][b];
            g_M[c * LT + b] = m;
        }
#pragma unroll
    for (int a = 0; a < LT; a++) {
#pragma unroll
        for (int b = 0; b < LT; b++) g_Tm[a * LT + b] = T[a][b];
        g_noise[a] = expf(log_noise[a]);
    }
}

// =====================================================================
// RBF kernels. mode 0: Cxx ; mode 1: Cx into B ; mode 2: A_c
// =====================================================================
__global__ void k_rbf(const float* __restrict__ X1, const float* __restrict__ X2,
                      const float* __restrict__ log_ls, int mode)
{
    __shared__ float xs1[16][8];
    __shared__ float xs2[16][8];
    int tid = threadIdx.x;
    int bx = blockIdx.x, by = blockIdx.y;
    if (tid < 128) {
        xs1[tid >> 3][tid & 7] = X1[(by * 16 + (tid >> 3)) * 8 + (tid & 7)];
    } else {
        int q = tid - 128;
        xs2[q >> 3][q & 7] = X2[(bx * 16 + (q >> 3)) * 8 + (q & 7)];
    }
    __syncthreads();
    int tx = tid & 15, ty = tid >> 4;
    float inv_ls2 = expf(-2.0f * log_ls[0]);
    float d2 = 0.0f;
#pragma unroll
    for (int d = 0; d < 8; d++) {
        float df = xs1[ty][d] - xs2[tx][d];
        d2 += df * df;
    }
    float kv = expf(-0.5f * d2 * inv_ls2);
    int i = by * 16 + ty, j = bx * 16 + tx;
    if (mode == 0) {
        g_Cxx[(size_t)i * NP + j] = kv;
    } else if (mode == 1) {
#pragma unroll
        for (int c = 0; c < LT; c++)
            g_B[(size_t)c * NP * NTOT + (size_t)i * NTOT + j] = kv;
    } else {
        float dg = (i == j) ? 1.0f : 0.0f;
#pragma unroll
        for (int c = 0; c < LT; c++)
            g_A[(size_t)c * NP * NP + (size_t)i * NP + j] = g_lambda[c] * kv + dg;
    }
}

// ytilde into column 1024 of each B_c + zero pad columns, coalesced.
__global__ void k_y(const float* __restrict__ Y)
{
    int idx = blockIdx.x * blockDim.x + threadIdx.x;   // < 4*1024*128
    if (idx >= LT * NP * 128) return;
    int p = idx & 127;
    int i = (idx >> 7) & 1023;
    int c = idx >> 17;
    float v = 0.0f;
    if (p == 0) {
#pragma unroll
        for (int a = 0; a < LT; a++) v += g_R[c * LT + a] * Y[i * LT + a];
    }
    g_B[(size_t)c * NP * NTOT + (size_t)i * NTOT + 1024 + p] = v;
}

// =====================================================================
// potf2 (kb=0 only): factor 64x64 diag block + produce L^{-1}
// =====================================================================
__global__ void k_potf2(int kb)
{
    int c = blockIdx.z;
    float* Ad = g_A + (size_t)c * NP * NP + (size_t)kb * 64 * NP + (size_t)kb * 64;
    float* Li = g_Linv + ((size_t)c * NKB + kb) * 64 * 64;
    __shared__ float s[64][65];
    __shared__ float vi[64][65];
    __shared__ float sdiag[64];
    int tid = threadIdx.x;
    int r = tid & 63, q = tid >> 6;
    for (int p = tid; p < 64 * 64; p += 256) {
        int rr = p >> 6, qq = p & 63;
        s[rr][qq] = Ad[(size_t)rr * NP + qq];
        vi[rr][qq] = (rr == qq) ? 1.0f : 0.0f;
    }
    __syncthreads();
#pragma unroll 1
    for (int j = 0; j < 64; j++) {
        float d = rsqrtf(s[j][j]);
        if (q == 0 && r > j)  s[r][j] *= d;
        if (q == 1 && r <= j) vi[j][r] *= d;
        if (q == 2 && r == j) sdiag[j] = s[j][j] * d;
        __syncthreads();
        if (r > j) {
            float sij = s[r][j];
            for (int t = j + 1 + q; t < 64; t += 4)
                s[r][t] -= sij * s[t][j];
            for (int t = q; t <= j; t += 4)
                vi[r][t] -= sij * vi[j][t];
        }
        __syncthreads();
    }
    for (int p = tid; p < 64 * 64; p += 256) {
        int rr = p >> 6, qq = p & 63;
        if (qq < rr) Ad[(size_t)rr * NP + qq] = s[rr][qq];
        else if (qq == rr) Ad[(size_t)rr * NP + qq] = sdiag[rr];
        Li[p] = vi[rr][qq];
    }
}

// =====================================================================
// combo1 (per kb): panel TRSM tiles + B diag-block solve, one launch.
// Additionally emits split-bf16 copies of its outputs:
//   jobA -> g_Ph/g_Pl  (panel, [m][k] k-contiguous, ld 64)
//   jobB -> g_Qh/g_Ql  (solved B rows transposed into Q slab kb)
// =====================================================================
__global__ void k_combo1(int kb, int rem)
{
    int c = blockIdx.z;
    const float* Li = g_Linv + ((size_t)c * NKB + kb) * 4096;
    int panelTiles = rem >> 6;
    int bx = blockIdx.x;
    __shared__ float As[16][68];
    __shared__ float Bs[16][68];
    __shared__ float sT[64][65];   // jobB transpose bounce
    int tid = threadIdx.x, tx = tid & 15, ty = tid >> 4;
    unsigned long long accP[4][2];
#pragma unroll
    for (int i = 0; i < 4; i++) { accP[i][0] = 0ull; accP[i][1] = 0ull; }

    bool isB = (bx >= panelTiles);
    int nb = bx - panelTiles;
    const float* Aop; const float* Bop; float* Cop;
    int lda, ldb, ldc; bool tb;
    if (!isB) {
        float* panel = g_A + (size_t)c * NP * NP + (size_t)(kb + 1) * 64 * NP + (size_t)kb * 64;
        Aop = panel + (size_t)bx * 64 * NP; lda = NP;
        Bop = Li; ldb = 64; tb = true;
        Cop = (float*)Aop; ldc = NP;
    } else {
        float* Bk = g_B + (size_t)c * NP * NTOT + (size_t)kb * 64 * NTOT;
        Aop = Li; lda = 64; tb = false;
        Bop = Bk + nb * 64; ldb = NTOT;
        Cop = (float*)Bop; ldc = NTOT;
    }
    for (int k0 = 0; k0 < 64; k0 += 16) {
        {
            int kl = tid & 15, ml = tid >> 4;
#pragma unroll
            for (int p = 0; p < 4; p++)
                As[kl][ml + p * 16] = Aop[(size_t)(ml + p * 16) * lda + (k0 + kl)];
        }
        if (!tb) {
            int nl = tid & 63, kl = tid >> 6;
#pragma unroll
            for (int p = 0; p < 4; p++)
                Bs[kl + p * 4][nl] = Bop[(size_t)(k0 + kl + p * 4) * ldb + nl];
        } else {
            int kl = tid & 15, nl = tid >> 4;
#pragma unroll
            for (int p = 0; p < 4; p++)
                Bs[kl][nl + p * 16] = Bop[(size_t)(nl + p * 16) * ldb + (k0 + kl)];
        }
        __syncthreads();
#pragma unroll
        for (int kk = 0; kk < 16; kk++) {
            float4 av = *(const float4*)&As[kk][ty * 4];
            float4 bv = *(const float4*)&Bs[kk][tx * 4];
            unsigned long long bp0 = f2pack(bv.x, bv.y);
            unsigned long long bp1 = f2pack(bv.z, bv.w);
            float a_[4] = {av.x, av.y, av.z, av.w};
#pragma unroll
            for (int i = 0; i < 4; i++) {
                unsigned long long ap = f2pack(a_[i], a_[i]);
                f2fma(accP[i][0], ap, bp0);
                f2fma(accP[i][1], ap, bp1);
            }
        }
        __syncthreads();
    }
    __nv_bfloat16* Ph = g_Ph + (size_t)c * 960 * 64;
    __nv_bfloat16* Pl = g_Pl + (size_t)c * 960 * 64;
#pragma unroll
    for (int i = 0; i < 4; i++) {
        float v[4];
        f2unpack(accP[i][0], v[0], v[1]);
        f2unpack(accP[i][1], v[2], v[3]);
        float* p = Cop + (size_t)(ty * 4 + i) * ldc + tx * 4;
        p[0] = v[0]; p[1] = v[1]; p[2] = v[2]; p[3] = v[3];
        if (!isB) {
            int mloc = bx * 64 + ty * 4 + i;
            __nv_bfloat16 h[4], l[4];
#pragma unroll
            for (int t = 0; t < 4; t++) bfsplit(v[t], h[t], l[t]);
            __nv_bfloat162 hp[2] = {__halves2bfloat162(h[0], h[1]), __halves2bfloat162(h[2], h[3])};
            __nv_bfloat162 lp[2] = {__halves2bfloat162(l[0], l[1]), __halves2bfloat162(l[2], l[3])};
            *(int2*)(Ph + (size_t)mloc * 64 + tx * 4) = *(int2*)hp;
            *(int2*)(Pl + (size_t)mloc * 64 + tx * 4) = *(int2*)lp;
        } else {
#pragma unroll
            for (int t = 0; t < 4; t++) sT[ty * 4 + i][tx * 4 + t] = v[t];
        }
    }
    if (isB) {
        __syncthreads();
        // transposed split writes: Q[n][kb*64 + k]
        int nl = tid >> 2, kg = tid & 3;
        size_t qoff = (size_t)c * NTOT * NP + (size_t)(nb * 64 + nl) * NP + (size_t)kb * 64 + kg * 16;
#pragma unroll
        for (int g = 0; g < 2; g++) {
            __nv_bfloat162 hp[4], lp[4];
#pragma unroll
            for (int t = 0; t < 4; t++) {
                float a0 = sT[kg * 16 + g * 8 + t * 2 + 0][nl];
                float a1 = sT[kg * 16 + g * 8 + t * 2 + 1][nl];
                __nv_bfloat16 h0, l0, h1, l1;
                bfsplit(a0, h0, l0);
                bfsplit(a1, h1, l1);
                hp[t] = __halves2bfloat162(h0, h1);
                lp[t] = __halves2bfloat162(l0, l1);
            }
            *(int4*)(g_Qh + qoff + g * 8) = *(int4*)hp;
            *(int4*)(g_Ql + qoff + g * 8) = *(int4*)lp;
        }
    }
}

// =====================================================================
// combo2 (per kb) via split-bf16 HMMA on PRE-SPLIT operands:
//   jobA (bx < tilesA, lower): A_trail -= panel * panel^T   (g_Ph/g_Pl)
//   jobB:                      B[kb+1:] -= panel * B_kb     (g_Qh/g_Ql slab)
// CTA tile 128x128, K=64 (two 32-chunks). 8 warps (4m x 2n).
// CTA (0,0,jobA) factors the next 64x64 diag block (fused potf2).
// =====================================================================
constexpr int CRS = 40;  // smem row stride (bf16 elems)

__global__ __launch_bounds__(256)
void k_combo2_mma(int kb, int rem)
{
    __shared__ __align__(16) __nv_bfloat16 stage[4 * 128 * CRS];  // 40960 B
    __nv_bfloat16* sAh = stage;
    __nv_bfloat16* sAl = stage + 128 * CRS;
    __nv_bfloat16* sBh = stage + 2 * 128 * CRS;
    __nv_bfloat16* sBl = stage + 3 * 128 * CRS;
    float* pool = (float*)stage;     // aliased for fused potf2 (33792 B)

    int c = blockIdx.z;
    int tilesA = (rem + 127) >> 7;
    int bx = blockIdx.x, mb = blockIdx.y;
    bool jobA = bx < tilesA;
    if (jobA && bx > mb) return;
    const __nv_bfloat16* Ph = g_Ph + (size_t)c * 960 * 64;
    const __nv_bfloat16* Pl = g_Pl + (size_t)c * 960 * 64;
    const __nv_bfloat16* Qh = g_Qh + (size_t)c * NTOT * NP;
    const __nv_bfloat16* Ql = g_Ql + (size_t)c * NTOT * NP;
    const int M = rem;
    float* Cop; int ldc; int N; int col0;
    if (jobA) {
        Cop = g_A + (size_t)c * NP * NP + (size_t)(kb + 1) * 64 * NP + (size_t)(kb + 1) * 64;
        ldc = NP; N = rem; col0 = bx * 128;
    } else {
        Cop = g_B + (size_t)c * NP * NTOT + (size_t)(kb + 1) * 64 * NTOT;
        ldc = NTOT; N = NTOT; col0 = (bx - tilesA) * 128;
    }
    const int row0 = mb * 128;
    int tid = threadIdx.x;
    int w = tid >> 5, lane = tid & 31;
    int wm = w & 3, wn = w >> 2;

    uint32_t bAh = smem_u32(sAh), bBh = smem_u32(sBh);
    uint32_t bAl = smem_u32(sAl), bBl = smem_u32(sBl);

    float acc[2][8][4];
#pragma unroll
    for (int i = 0; i < 2; i++)
#pragma unroll
        for (int j = 0; j < 8; j++)
#pragma unroll
            for (int v = 0; v < 4; v++) acc[i][j][v] = 0.0f;

    const uint32_t lmo = (uint32_t)((lane & 15) * CRS + ((lane >> 4) << 3)) * 2u;

#pragma unroll 1
    for (int k0 = 0; k0 < 64; k0 += 32) {
        // ---- stage A: g_Ph/g_Pl rows row0..row0+127, 32 k (4 int4/row) ----
#pragma unroll
        for (int it = 0; it < 2; it++) {
            int idx = tid + it * 256;          // 0..511
            int r = idx >> 2, ch = idx & 3;
            int m = row0 + r; if (m >= M) m = M - 1;
            *(int4*)(sAh + r * CRS + ch * 8) = *(const int4*)(Ph + (size_t)m * 64 + k0 + ch * 8);
            *(int4*)(sAl + r * CRS + ch * 8) = *(const int4*)(Pl + (size_t)m * 64 + k0 + ch * 8);
        }
        // ---- stage B ----
        if (jobA) {
#pragma unroll
            for (int it = 0; it < 2; it++) {
                int idx = tid + it * 256;
                int r = idx >> 2, ch = idx & 3;
                int n = col0 + r; if (n >= N) n = N - 1;
                *(int4*)(sBh + r * CRS + ch * 8) = *(const int4*)(Ph + (size_t)n * 64 + k0 + ch * 8);
                *(int4*)(sBl + r * CRS + ch * 8) = *(const int4*)(Pl + (size_t)n * 64 + k0 + ch * 8);
            }
        } else {
            size_t kbase = (size_t)kb * 64 + k0;
#pragma unroll
            for (int it = 0; it < 2; it++) {
                int idx = tid + it * 256;
                int r = idx >> 2, ch = idx & 3;
                int n = col0 + r;
                *(int4*)(sBh + r * CRS + ch * 8) = *(const int4*)(Qh + (size_t)n * NP + kbase + ch * 8);
                *(int4*)(sBl + r * CRS + ch * 8) = *(const int4*)(Ql + (size_t)n * NP + kbase + ch * 8);
            }
        }
        __syncthreads();
        // ---- compute: validated fragment pattern ----
#pragma unroll
        for (int ks = 0; ks < 32; ks += 16) {
            uint32_t Ah[2][4], Al[2][4];
#pragma unroll
            for (int mt = 0; mt < 2; mt++) {
                uint32_t off = (uint32_t)((wm * 32 + mt * 16) * CRS + ks) * 2u + lmo;
                ldmx4(Ah[mt], bAh + off);
                ldmx4(Al[mt], bAl + off);
            }
#pragma unroll
            for (int np = 0; np < 4; np++) {
                uint32_t Bh[4], Bl[4];
                uint32_t off = (uint32_t)((wn * 64 + np * 16) * CRS + ks) * 2u + lmo;
                ldmx4(Bh, bBh + off);
                ldmx4(Bl, bBl + off);
#pragma unroll
                for (int sub = 0; sub < 2; sub++) {
                    int nt = np * 2 + sub;
#pragma unroll
                    for (int mt = 0; mt < 2; mt++) {
                        mma16816(acc[mt][nt], Ah[mt], Bh[sub], Bh[sub + 2]);
                        mma16816(acc[mt][nt], Ah[mt], Bl[sub], Bl[sub + 2]);
                        mma16816(acc[mt][nt], Al[mt], Bh[sub], Bh[sub + 2]);
                    }
                }
            }
        }
        __syncthreads();
    }

    // ---- epilogue: C -= acc (RMW); capture diag block for fused potf2 ----
    bool fuse = jobA && bx == 0 && mb == 0 && (kb + 1 < NKB);
    int gr = lane >> 2, gc = (lane & 3) << 1;
#pragma unroll
    for (int mt = 0; mt < 2; mt++) {
#pragma unroll
        for (int half = 0; half < 2; half++) {
            int m = row0 + wm * 32 + mt * 16 + gr + half * 8;
            if (m >= M) continue;
#pragma unroll
            for (int nt = 0; nt < 8; nt++) {
                int n = col0 + wn * 64 + nt * 8 + gc;
                if (n >= N) continue;
                float a0 = acc[mt][nt][half * 2 + 0];
                float a1 = acc[mt][nt][half * 2 + 1];
                float* p = Cop + (size_t)m * ldc + n;
                float2 o = *(float2*)p;
                o.x -= a0; o.y -= a1;
                *(float2*)p = o;
                if (fuse && m < 64 && n < 64) {
                    pool[m * 65 + n + 0] = o.x;
                    pool[m * 65 + n + 1] = o.y;
                }
            }
        }
    }

    if (fuse) {
        // ---- fused potf2(kb+1): factor + invert 64x64 from pool ----
        float* s  = pool;          // [64][65]
        float* vi = pool + 4224;   // [64][65]
        float* sd = pool + 8384;   // [64]
        int r = tid & 63, q = tid >> 6;
        for (int p = tid; p < 64 * 64; p += 256)
            vi[(p >> 6) * 65 + (p & 63)] = ((p >> 6) == (p & 63)) ? 1.0f : 0.0f;
        __syncthreads();
#pragma unroll 1
        for (int j = 0; j < 64; j++) {
            float d = rsqrtf(s[j * 65 + j]);
            if (q == 0 && r > j)  s[r * 65 + j] *= d;
            if (q == 1 && r <= j) vi[j * 65 + r] *= d;
            if (q == 2 && r == j) sd[j] = s[j * 65 + j] * d;
            __syncthreads();
            if (r > j) {
                float sij = s[r * 65 + j];
                for (int t = j + 1 + q; t < 64; t += 4)
                    s[r * 65 + t] -= sij * s[t * 65 + j];
                for (int t = q; t <= j; t += 4)
                    vi[r * 65 + t] -= sij * vi[j * 65 + t];
            }
            __syncthreads();
        }
        int kbn = kb + 1;
        float* Ad = g_A + (size_t)c * NP * NP + (size_t)kbn * 64 * NP + (size_t)kbn * 64;
        float* Li = g_Linv + ((size_t)c * NKB + kbn) * 4096;
        for (int p = tid; p < 64 * 64; p += 256) {
            int rr = p >> 6, qq = p & 63;
            if (qq < rr) Ad[(size_t)rr * NP + qq] = s[rr * 65 + qq];
            else if (qq == rr) Ad[(size_t)rr * NP + qq] = sd[rr];
            Li[p] = vi[rr * 65 + qq];
        }
    }
}

// =====================================================================
// H GEMM via mma.sync bf16 split: H = Qh Qh^T + Qh Ql^T + Ql Qh^T
// =====================================================================
constexpr int QRS = 40;

__global__ __launch_bounds__(256)
void k_hgemm_mma()
{
    int nb = blockIdx.x, mb = blockIdx.y;
    if (nb > mb && nb != (int)gridDim.x - 1) return;
    int c = blockIdx.z;
    const __nv_bfloat16* Qh = g_Qh + (size_t)c * NTOT * NP;
    const __nv_bfloat16* Ql = g_Ql + (size_t)c * NTOT * NP;
    const int row0 = mb * 128, col0 = nb * 128;

    __shared__ __align__(16) __nv_bfloat16 sAh[128 * QRS];
    __shared__ __align__(16) __nv_bfloat16 sBh[128 * QRS];
    __shared__ __align__(16) __nv_bfloat16 sAl[128 * QRS];
    __shared__ __align__(16) __nv_bfloat16 sBl[128 * QRS];

    int tid = threadIdx.x;
    int w = tid >> 5, lane = tid & 31;
    int wm = w & 3, wn = w >> 2;

    uint32_t bAh = smem_u32(sAh), bBh = smem_u32(sBh);
    uint32_t bAl = smem_u32(sAl), bBl = smem_u32(sBl);

    float acc[2][8][4];
#pragma unroll
    for (int i = 0; i < 2; i++)
#pragma unroll
        for (int j = 0; j < 8; j++)
#pragma unroll
            for (int v = 0; v < 4; v++) acc[i][j][v] = 0.0f;

    const uint32_t lmo = (uint32_t)((lane & 15) * QRS + ((lane >> 4) << 3)) * 2u;

#pragma unroll 1
    for (int k0 = 0; k0 < NP; k0 += 32) {
#pragma unroll
        for (int it = 0; it < 2; it++) {
            int idx = tid + it * 256;
            int r = idx >> 2, ch = idx & 3;
            const int4* gah = (const int4*)(Qh + (size_t)(row0 + r) * NP + k0) + ch;
            const int4* gbh = (const int4*)(Qh + (size_t)(col0 + r) * NP + k0) + ch;
            const int4* gal = (const int4*)(Ql + (size_t)(row0 + r) * NP + k0) + ch;
            const int4* gbl = (const int4*)(Ql + (size_t)(col0 + r) * NP + k0) + ch;
            *(int4*)(sAh + r * QRS + ch * 8) = *gah;
            *(int4*)(sBh + r * QRS + ch * 8) = *gbh;
            *(int4*)(sAl + r * QRS + ch * 8) = *gal;
            *(int4*)(sBl + r * QRS + ch * 8) = *gbl;
        }
        __syncthreads();
#pragma unroll
        for (int ks = 0; ks < 32; ks += 16) {
            uint32_t Ah[2][4], Al[2][4];
#pragma unroll
            for (int mt = 0; mt < 2; mt++) {
                uint32_t off = (uint32_t)((wm * 32 + mt * 16) * QRS + ks) * 2u + lmo;
                ldmx4(Ah[mt], bAh + off);
                ldmx4(Al[mt], bAl + off);
            }
#pragma unroll
            for (int np = 0; np < 4; np++) {
                uint32_t Bh[4], Bl[4];
                uint32_t off = (uint32_t)((wn * 64 + np * 16) * QRS + ks) * 2u + lmo;
                ldmx4(Bh, bBh + off);
                ldmx4(Bl, bBl + off);
#pragma unroll
                for (int sub = 0; sub < 2; sub++) {
                    int nt = np * 2 + sub;
#pragma unroll
                    for (int mt = 0; mt < 2; mt++) {
                        mma16816(acc[mt][nt], Ah[mt], Bh[sub], Bh[sub + 2]);
                        mma16816(acc[mt][nt], Ah[mt], Bl[sub], Bl[sub + 2]);
                        mma16816(acc[mt][nt], Al[mt], Bh[sub], Bh[sub + 2]);
                    }
                }
            }
        }
        __syncthreads();
    }

    float* H = g_H + (size_t)c * NP * NTOT;
    int gr = lane >> 2, gc = (lane & 3) << 1;
#pragma unroll
    for (int mt = 0; mt < 2; mt++) {
        int m = row0 + wm * 32 + mt * 16 + gr;
#pragma unroll
        for (int nt = 0; nt < 8; nt++) {
            int n = col0 + wn * 64 + nt * 8 + gc;
            *(float2*)(H + (size_t)m * NTOT + n)       = make_float2(acc[mt][nt][0], acc[mt][nt][1]);
            *(float2*)(H + (size_t)(m + 8) * NTOT + n) = make_float2(acc[mt][nt][2], acc[mt][nt][3]);
        }
    }
}

// =====================================================================
// Symmetrize H: copy lower triangle -> upper (cols < 1024 only)
// =====================================================================
__global__ void k_symH()
{
    int tc = blockIdx.x, tr = blockIdx.y;
    if (tc < tr) return;
    int c = blockIdx.z;
    float* H = g_H + (size_t)c * NP * NTOT;
    __shared__ float s[32][33];
    int x = threadIdx.x, y0 = threadIdx.y;
    for (int yy = y0; yy < 32; yy += 8)
        s[yy][x] = H[(size_t)(tc * 32 + yy) * NTOT + tr * 32 + x];
    __syncthreads();
    for (int yy = y0; yy < 32; yy += 8) {
        int i = tr * 32 + yy, j = tc * 32 + x;
        if (j > i) H[(size_t)i * NTOT + j] = s[x][yy];
    }
}

// =====================================================================
// Final outputs
// =====================================================================
__global__ void k_fmean(float* __restrict__ out)
{
    int idx = blockIdx.x * blockDim.x + threadIdx.x;
    if (idx >= 4096) return;
    int b = idx >> 10, j = idx & 1023;
    float v = 0.0f;
#pragma unroll
    for (int c = 0; c < LT; c++)
        v += g_M[c * LT + b] * g_H[(size_t)c * NP * NTOT + (size_t)j * NTOT + 1024];
    out[OFF_FMEAN + idx] = v;
    out[OFF_OUT4 + (size_t)j * LT + b] = v;
}

__global__ void k_output(float* __restrict__ out)
{
    size_t t = (size_t)blockIdx.x * blockDim.x + threadIdx.x;
    if (t >= (size_t)4096 * 1024) return;
    int g = (int)(t & 1023);
    size_t ig = t >> 10;
    int a = (int)(ig >> 10);
    int i = (int)(ig & 1023);
    int b = g >> 8;
    int j0 = (g & 255) << 2;
    float4 cxx = *(const float4*)&g_Cxx[(size_t)i * NP + j0];
    float Tab = g_Tm[a * LT + b];
    float4 acc;
    acc.x = Tab * cxx.x;
    acc.y = Tab * cxx.y;
    acc.z = Tab * cxx.z;
    acc.w = Tab * cxx.w;
#pragma unroll
    for (int c = 0; c < LT; c++) {
        float mm = g_M[c * LT + a] * g_M[c * LT + b];
        float4 h = *(const float4*)&g_H[(size_t)c * NP * NTOT + (size_t)i * NTOT + j0];
        acc.x -= mm * h.x;
        acc.y -= mm * h.y;
        acc.z -= mm * h.z;
        acc.w -= mm * h.w;
    }
    size_t col0 = (size_t)b * 1024 + j0;
    *(float4*)&out[OFF_FVAR + ig * 4096 + col0] = acc;
    float4 nz = make_float4(0.f, 0.f, 0.f, 0.f);
    if (ig >= col0 && ig < col0 + 4) {
        float nv = g_noise[a];
        int jj = (int)(ig - col0);
        if (jj == 0) nz.x = nv;
        else if (jj == 1) nz.y = nv;
        else if (jj == 2) nz.z = nv;
        else nz.w = nv;
    }
    *(float4*)&out[OFF_NOISE + ig * 4096 + col0] = nz;
}

// =====================================================================
// Host side
// =====================================================================
extern "C" void kernel_launch(void* const* d_in, const int* in_sizes, int n_in,
                              void* d_out, int out_size)
{
    const float* X        = (const float*)d_in[0];
    const float* test_X   = (const float*)d_in[1];
    const float* Y        = (const float*)d_in[2];
    const float* lnoise   = (const float*)d_in[3];
    const float* cfac     = (const float*)d_in[4];
    const float* lvar     = (const float*)d_in[5];
    const float* lls      = (const float*)d_in[6];
    int rank = in_sizes[4] / LT;
    float* out = (float*)d_out;

    k_setup<<<1, 32>>>(cfac, lvar, lnoise, rank);
    dim3 rg(64, 64);
    k_rbf<<<rg, 256>>>(X, X, lls, 2);           // A_c = lambda_c*C + I
    k_rbf<<<rg, 256>>>(X, test_X, lls, 1);      // Cx into B_c
    k_rbf<<<rg, 256>>>(test_X, test_X, lls, 0); // Cxx
    k_y<<<(LT * NP * 128 + 255) / 256, 256>>>(Y);

    // ---- batched blocked Cholesky fused with forward solve ----
    // combo1 emits split-bf16 panel + Q slab; combo2 runs on tensor cores.
    k_potf2<<<dim3(1, 1, LT), 256>>>(0);
    for (int kb = 0; kb < NKB; kb++) {
        int rem = NP - 64 * (kb + 1);
        k_combo1<<<dim3((rem >> 6) + (NTOT >> 6), 1, LT), 256>>>(kb, rem);
        if (rem > 0) {
            int tilesA = (rem + 127) >> 7;
            k_combo2_mma<<<dim3(tilesA + (NTOT >> 7), tilesA, LT), 256>>>(kb, rem);
        }
    }

    // ---- H = Q Q^T on tensor cores (Q written by combo1) ----
    k_hgemm_mma<<<dim3(NTOT / 128, NP / 128, LT), 256>>>();
    k_symH<<<dim3(32, 32, LT), dim3(32, 8)>>>();

    // ---- outputs ----
    k_fmean<<<16, 256>>>(out);
    k_output<<<16384, 256>>>(out);
}

// round 13
// speedup vs baseline: 1.5230x; 1.5230x over previous
#include <cuda_runtime.h>
#include <cuda_bf16.h>
#include <math.h>
#include <stdint.h>

// Problem constants (fixed instance)
constexpr int NP   = 1024;   // N == N_ (train/test points)
constexpr int LT   = 4;      // tasks
constexpr int RNK_MAX = 8;
constexpr int NTOT = 1152;   // RHS width: 1024 Cx cols + 1 ytilde col + pad to 9*128
constexpr int NKB  = 16;     // 1024 / 64 block steps

// Output offsets (fp32 elements)
constexpr size_t OFF_FMEAN = 0;
constexpr size_t OFF_FVAR  = 4096;
constexpr size_t OFF_NOISE = OFF_FVAR + (size_t)4096 * 4096;
constexpr size_t OFF_OUT4  = OFF_NOISE + (size_t)4096 * 4096;

// -------- device scratch (static, no allocation) --------
__device__ float g_A[LT * NP * NP];          // lambda_c*C + I, then Cholesky L (lower)
__device__ float g_B[LT * NP * NTOT];        // RHS -> forward-solved P_c (and w_c in col 1024)
__device__ float g_H[LT * NP * NTOT];        // H_c = P_c^T * P_c  (col 1024 = g_c)
__device__ float g_Cxx[NP * NP];             // rbf(test_X, test_X)
__device__ float g_Linv[LT * NKB * 64 * 64]; // per-step 64x64 diag-block inverses
__device__ __nv_bfloat16 g_Qh[LT * (size_t)NTOT * NP]; // Q = P^T, bf16 hi
__device__ __nv_bfloat16 g_Ql[LT * (size_t)NTOT * NP]; // Q residual, bf16 lo
__device__ float g_lambda[LT];
__device__ float g_R[LT * LT];               // R = U^T Dn^{-1/2}
__device__ float g_M[LT * LT];               // M = R * T
__device__ float g_Tm[LT * LT];              // task_K
__device__ float g_noise[LT];                // exp(log_noise)

// -------- packed fp32x2 helpers --------
__device__ __forceinline__ unsigned long long f2pack(float lo, float hi)
{
    unsigned long long r;
    asm("mov.b64 %0, {%1, %2};" : "=l"(r) : "f"(lo), "f"(hi));
    return r;
}
__device__ __forceinline__ void f2unpack(unsigned long long v, float& lo, float& hi)
{
    asm("mov.b64 {%0, %1}, %2;" : "=f"(lo), "=f"(hi) : "l"(v));
}
__device__ __forceinline__ void f2fma(unsigned long long& d,
                                      unsigned long long a, unsigned long long b)
{
    asm("fma.rn.f32x2 %0, %1, %2, %3;" : "=l"(d) : "l"(a), "l"(b), "l"(d));
}

// -------- mma.sync / ldmatrix / cp.async helpers --------
__device__ __forceinline__ uint32_t smem_u32(const void* p)
{
    uint32_t a;
    asm("{ .reg .u64 t; cvta.to.shared.u64 t, %1; cvt.u32.u64 %0, t; }" : "=r"(a) : "l"(p));
    return a;
}
__device__ __forceinline__ void ldmx4(uint32_t* r, uint32_t addr)
{
    asm volatile("ldmatrix.sync.aligned.m8n8.x4.shared.b16 {%0,%1,%2,%3}, [%4];"
        : "=r"(r[0]), "=r"(r[1]), "=r"(r[2]), "=r"(r[3]) : "r"(addr));
}
__device__ __forceinline__ void mma16816(float* d, const uint32_t* a,
                                         uint32_t b0, uint32_t b1)
{
    asm volatile(
        "mma.sync.aligned.m16n8k16.row.col.f32.bf16.bf16.f32 "
        "{%0,%1,%2,%3}, {%4,%5,%6,%7}, {%8,%9}, {%0,%1,%2,%3};"
        : "+f"(d[0]), "+f"(d[1]), "+f"(d[2]), "+f"(d[3])
        : "r"(a[0]), "r"(a[1]), "r"(a[2]), "r"(a[3]), "r"(b0), "r"(b1));
}
__device__ __forceinline__ void cpa16(uint32_t saddr, const void* gptr)
{
    asm volatile("cp.async.cg.shared.global [%0], [%1], 16;" :: "r"(saddr), "l"(gptr));
}
__device__ __forceinline__ void cpa_commit()
{
    asm volatile("cp.async.commit_group;" ::: "memory");
}
template <int N>
__device__ __forceinline__ void cpa_wait()
{
    asm volatile("cp.async.wait_group %0;" :: "n"(N) : "memory");
}

// =====================================================================
// Small setup: task_K, 4x4 Jacobi eigendecomposition, R, M (fp32, 10 sweeps)
// =====================================================================
__global__ void k_setup(const float* __restrict__ cf,
                        const float* __restrict__ log_var,
                        const float* __restrict__ log_noise,
                        int rank)
{
    if (threadIdx.x != 0) return;
    float T[LT][LT], Tt[LT][LT], U[LT][LT], sv[LT];
#pragma unroll
    for (int a = 0; a < LT; a++) sv[a] = expf(-0.5f * log_noise[a]);
    for (int a = 0; a < LT; a++)
        for (int b = 0; b < LT; b++) {
            float s = 0.0f;
            for (int r = 0; r < rank && r < RNK_MAX; r++)
                s += cf[a * rank + r] * cf[b * rank + r];
            if (a == b) s += expf(log_var[a]);
            T[a][b] = s;
        }
#pragma unroll
    for (int a = 0; a < LT; a++)
#pragma unroll
        for (int b = 0; b < LT; b++) {
            Tt[a][b] = sv[a] * sv[b] * T[a][b];
            U[a][b] = (a == b) ? 1.0f : 0.0f;
        }
#pragma unroll 1
    for (int sweep = 0; sweep < 10; sweep++) {
#pragma unroll
        for (int p = 0; p < LT; p++)
#pragma unroll
            for (int q = p + 1; q < LT; q++) {
                float apq = Tt[p][q];
                if (fabsf(apq) < 1e-30f) continue;
                float tau = (Tt[q][q] - Tt[p][p]) / (2.0f * apq);
                float tt = ((tau >= 0.0f) ? 1.0f : -1.0f) / (fabsf(tau) + sqrtf(1.0f + tau * tau));
                float cc = rsqrtf(1.0f + tt * tt);
                float ss = tt * cc;
#pragma unroll
                for (int k = 0; k < LT; k++) {
                    float akp = Tt[k][p], akq = Tt[k][q];
                    Tt[k][p] = cc * akp - ss * akq;
                    Tt[k][q] = ss * akp + cc * akq;
                }
#pragma unroll
                for (int k = 0; k < LT; k++) {
                    float apk = Tt[p][k], aqk = Tt[q][k];
                    Tt[p][k] = cc * apk - ss * aqk;
                    Tt[q][k] = ss * apk + cc * aqk;
                }
#pragma unroll
                for (int k = 0; k < LT; k++) {
                    float ukp = U[k][p], ukq = U[k][q];
                    U[k][p] = cc * ukp - ss * ukq;
                    U[k][q] = ss * ukp + cc * ukq;
                }
            }
    }
    float R[LT][LT];
#pragma unroll
    for (int c = 0; c < LT; c++) {
        g_lambda[c] = Tt[c][c];
#pragma unroll
        for (int a = 0; a < LT; a++) {
            R[c][a] = U[a][c] * sv[a];
            g_R[c * LT + a] = R[c][a];
        }
    }
#pragma unroll
    for (int c = 0; c < LT; c++)
#pragma unroll
        for (int b = 0; b < LT; b++) {
            float m = 0.0f;
#pragma unroll
            for (int a = 0; a < LT; a++) m += R[c][a] * T[a][b];
            g_M[c * LT + b] = m;
        }
#pragma unroll
    for (int a = 0; a < LT; a++) {
#pragma unroll
        for (int b = 0; b < LT; b++) g_Tm[a * LT + b] = T[a][b];
        g_noise[a] = expf(log_noise[a]);
    }
}

// =====================================================================
// RBF kernels. mode 0: Cxx ; mode 1: Cx into B ; mode 2: A_c
// =====================================================================
__global__ void k_rbf(const float* __restrict__ X1, const float* __restrict__ X2,
                      const float* __restrict__ log_ls, int mode)
{
    __shared__ float xs1[16][8];
    __shared__ float xs2[16][8];
    int tid = threadIdx.x;
    int bx = blockIdx.x, by = blockIdx.y;
    if (tid < 128) {
        xs1[tid >> 3][tid & 7] = X1[(by * 16 + (tid >> 3)) * 8 + (tid & 7)];
    } else {
        int q = tid - 128;
        xs2[q >> 3][q & 7] = X2[(bx * 16 + (q >> 3)) * 8 + (q & 7)];
    }
    __syncthreads();
    int tx = tid & 15, ty = tid >> 4;
    float inv_ls2 = expf(-2.0f * log_ls[0]);
    float d2 = 0.0f;
#pragma unroll
    for (int d = 0; d < 8; d++) {
        float df = xs1[ty][d] - xs2[tx][d];
        d2 += df * df;
    }
    float kv = expf(-0.5f * d2 * inv_ls2);
    int i = by * 16 + ty, j = bx * 16 + tx;
    if (mode == 0) {
        g_Cxx[(size_t)i * NP + j] = kv;
    } else if (mode == 1) {
#pragma unroll
        for (int c = 0; c < LT; c++)
            g_B[(size_t)c * NP * NTOT + (size_t)i * NTOT + j] = kv;
    } else {
        float dg = (i == j) ? 1.0f : 0.0f;
#pragma unroll
        for (int c = 0; c < LT; c++)
            g_A[(size_t)c * NP * NP + (size_t)i * NP + j] = g_lambda[c] * kv + dg;
    }
}

// ytilde into column 1024 of each B_c + zero pad columns, coalesced.
__global__ void k_y(const float* __restrict__ Y)
{
    int idx = blockIdx.x * blockDim.x + threadIdx.x;   // < 4*1024*128
    if (idx >= LT * NP * 128) return;
    int p = idx & 127;
    int i = (idx >> 7) & 1023;
    int c = idx >> 17;
    float v = 0.0f;
    if (p == 0) {
#pragma unroll
        for (int a = 0; a < LT; a++) v += g_R[c * LT + a] * Y[i * LT + a];
    }
    g_B[(size_t)c * NP * NTOT + (size_t)i * NTOT + 1024 + p] = v;
}

// =====================================================================
// potf2 (kb=0 only): factor 64x64 diag block + produce L^{-1}
// =====================================================================
__global__ void k_potf2(int kb)
{
    int c = blockIdx.z;
    float* Ad = g_A + (size_t)c * NP * NP + (size_t)kb * 64 * NP + (size_t)kb * 64;
    float* Li = g_Linv + ((size_t)c * NKB + kb) * 64 * 64;
    __shared__ float s[64][65];
    __shared__ float vi[64][65];
    __shared__ float sdiag[64];
    int tid = threadIdx.x;
    int r = tid & 63, q = tid >> 6;
    for (int p = tid; p < 64 * 64; p += 256) {
        int rr = p >> 6, qq = p & 63;
        s[rr][qq] = Ad[(size_t)rr * NP + qq];
        vi[rr][qq] = (rr == qq) ? 1.0f : 0.0f;
    }
    __syncthreads();
#pragma unroll 1
    for (int j = 0; j < 64; j++) {
        float d = rsqrtf(s[j][j]);
        if (q == 0 && r > j)  s[r][j] *= d;
        if (q == 1 && r <= j) vi[j][r] *= d;
        if (q == 2 && r == j) sdiag[j] = s[j][j] * d;
        __syncthreads();
        if (r > j) {
            float sij = s[r][j];
            for (int t = j + 1 + q; t < 64; t += 4)
                s[r][t] -= sij * s[t][j];
            for (int t = q; t <= j; t += 4)
                vi[r][t] -= sij * vi[j][t];
        }
        __syncthreads();
    }
    for (int p = tid; p < 64 * 64; p += 256) {
        int rr = p >> 6, qq = p & 63;
        if (qq < rr) Ad[(size_t)rr * NP + qq] = s[rr][qq];
        else if (qq == rr) Ad[(size_t)rr * NP + qq] = sdiag[rr];
        Li[p] = vi[rr][qq];
    }
}

// =====================================================================
// combo1 (per kb): panel TRSM tiles + B diag-block solve, one launch
// =====================================================================
__global__ void k_combo1(int kb, int rem)
{
    int c = blockIdx.z;
    const float* Li = g_Linv + ((size_t)c * NKB + kb) * 4096;
    int panelTiles = rem >> 6;
    int bx = blockIdx.x;
    __shared__ float As[16][68];
    __shared__ float Bs[16][68];
    int tid = threadIdx.x, tx = tid & 15, ty = tid >> 4;
    unsigned long long accP[4][2];
#pragma unroll
    for (int i = 0; i < 4; i++) { accP[i][0] = 0ull; accP[i][1] = 0ull; }

    const float* Aop; const float* Bop; float* Cop;
    int lda, ldb, ldc; bool tb;
    if (bx < panelTiles) {
        float* panel = g_A + (size_t)c * NP * NP + (size_t)(kb + 1) * 64 * NP + (size_t)kb * 64;
        Aop = panel + (size_t)bx * 64 * NP; lda = NP;
        Bop = Li; ldb = 64; tb = true;
        Cop = (float*)Aop; ldc = NP;
    } else {
        int nb = bx - panelTiles;
        float* Bk = g_B + (size_t)c * NP * NTOT + (size_t)kb * 64 * NTOT;
        Aop = Li; lda = 64; tb = false;
        Bop = Bk + nb * 64; ldb = NTOT;
        Cop = (float*)Bop; ldc = NTOT;
    }
    for (int k0 = 0; k0 < 64; k0 += 16) {
        {
            int kl = tid & 15, ml = tid >> 4;
#pragma unroll
            for (int p = 0; p < 4; p++)
                As[kl][ml + p * 16] = Aop[(size_t)(ml + p * 16) * lda + (k0 + kl)];
        }
        if (!tb) {
            int nl = tid & 63, kl = tid >> 6;
#pragma unroll
            for (int p = 0; p < 4; p++)
                Bs[kl + p * 4][nl] = Bop[(size_t)(k0 + kl + p * 4) * ldb + nl];
        } else {
            int kl = tid & 15, nl = tid >> 4;
#pragma unroll
            for (int p = 0; p < 4; p++)
                Bs[kl][nl + p * 16] = Bop[(size_t)(nl + p * 16) * ldb + (k0 + kl)];
        }
        __syncthreads();
#pragma unroll
        for (int kk = 0; kk < 16; kk++) {
            float4 av = *(const float4*)&As[kk][ty * 4];
            float4 bv = *(const float4*)&Bs[kk][tx * 4];
            unsigned long long bp0 = f2pack(bv.x, bv.y);
            unsigned long long bp1 = f2pack(bv.z, bv.w);
            float a_[4] = {av.x, av.y, av.z, av.w};
#pragma unroll
            for (int i = 0; i < 4; i++) {
                unsigned long long ap = f2pack(a_[i], a_[i]);
                f2fma(accP[i][0], ap, bp0);
                f2fma(accP[i][1], ap, bp1);
            }
        }
        __syncthreads();
    }
#pragma unroll
    for (int i = 0; i < 4; i++) {
        float v0, v1, v2, v3;
        f2unpack(accP[i][0], v0, v1);
        f2unpack(accP[i][1], v2, v3);
        float* p = Cop + (size_t)(ty * 4 + i) * ldc + tx * 4;
        p[0] = v0; p[1] = v1; p[2] = v2; p[3] = v3;
    }
}

// =====================================================================
// combo2 (per kb): trailing SYRK (lower tiles) + B off-diag update.
// 128x128 tiles, 8x8 micro via FFMA2 pairs. K=64.
// CTA (0,0,jobA) additionally factors the next 64x64 diag block.
// =====================================================================
__global__ __launch_bounds__(256, 2)
void k_combo2(int kb, int rem)
{
    __shared__ float pool[8448];
    float* Asb = pool;          // [16][132]
    float* Bsb = pool + 2112;   // [16][132]
    int c = blockIdx.z;
    int tilesA = (rem + 127) >> 7;
    int bx = blockIdx.x, mb = blockIdx.y;
    bool jobA = bx < tilesA;
    if (jobA && bx > mb) return;
    const float* panel = g_A + (size_t)c * NP * NP + (size_t)(kb + 1) * 64 * NP + (size_t)kb * 64;
    const float* Aop = panel;
    const int lda = NP;
    const int M = rem;
    const float* Bop; int ldb; bool tb; float* Cop; int ldc; int N; int col0;
    if (jobA) {
        Bop = panel; ldb = NP; tb = true;
        Cop = g_A + (size_t)c * NP * NP + (size_t)(kb + 1) * 64 * NP + (size_t)(kb + 1) * 64;
        ldc = NP; N = rem; col0 = bx * 128;
    } else {
        Bop = g_B + (size_t)c * NP * NTOT + (size_t)kb * 64 * NTOT;
        ldb = NTOT; tb = false;
        Cop = g_B + (size_t)c * NP * NTOT + (size_t)(kb + 1) * 64 * NTOT;
        ldc = NTOT; N = NTOT; col0 = (bx - tilesA) * 128;
    }
    const int row0 = mb * 128;
    int tid = threadIdx.x, tx = tid & 15, ty = tid >> 4;
    unsigned long long accP[8][4];
#pragma unroll
    for (int i = 0; i < 8; i++)
#pragma unroll
        for (int j = 0; j < 4; j++) accP[i][j] = 0ull;

    for (int k0 = 0; k0 < 64; k0 += 16) {
        {
            int rr = tid >> 2, c4 = (tid & 3) << 2;
#pragma unroll
            for (int h = 0; h < 2; h++) {
                int m = row0 + rr + h * 64;
                if (m >= M) m = M - 1;
                float4 v = *(const float4*)(Aop + (size_t)m * lda + k0 + c4);
                Asb[(c4 + 0) * 132 + rr + h * 64] = v.x;
                Asb[(c4 + 1) * 132 + rr + h * 64] = v.y;
                Asb[(c4 + 2) * 132 + rr + h * 64] = v.z;
                Asb[(c4 + 3) * 132 + rr + h * 64] = v.w;
            }
        }
        if (!tb) {
            int kk = tid >> 4, n8 = (tid & 15) << 3;
#pragma unroll
            for (int h = 0; h < 2; h++) {
                int n = col0 + n8 + h * 4;
                float4 v = *(const float4*)(Bop + (size_t)(k0 + kk) * ldb + n);
                *(float4*)&Bsb[kk * 132 + n8 + h * 4] = v;
            }
        } else {
            int rr = tid >> 2, c4 = (tid & 3) << 2;
#pragma unroll
            for (int h = 0; h < 2; h++) {
                int n = col0 + rr + h * 64;
                if (n >= N) n = N - 1;
                float4 v = *(const float4*)(Bop + (size_t)n * ldb + k0 + c4);
                Bsb[(c4 + 0) * 132 + rr + h * 64] = v.x;
                Bsb[(c4 + 1) * 132 + rr + h * 64] = v.y;
                Bsb[(c4 + 2) * 132 + rr + h * 64] = v.z;
                Bsb[(c4 + 3) * 132 + rr + h * 64] = v.w;
            }
        }
        __syncthreads();
#pragma unroll
        for (int kk = 0; kk < 16; kk++) {
            float4 a0 = *(const float4*)&Asb[kk * 132 + ty * 8];
            float4 a1 = *(const float4*)&Asb[kk * 132 + ty * 8 + 4];
            float4 b0 = *(const float4*)&Bsb[kk * 132 + tx * 8];
            float4 b1 = *(const float4*)&Bsb[kk * 132 + tx * 8 + 4];
            unsigned long long bp0 = f2pack(b0.x, b0.y);
            unsigned long long bp1 = f2pack(b0.z, b0.w);
            unsigned long long bp2 = f2pack(b1.x, b1.y);
            unsigned long long bp3 = f2pack(b1.z, b1.w);
            float av[8] = {a0.x, a0.y, a0.z, a0.w, a1.x, a1.y, a1.z, a1.w};
#pragma unroll
            for (int i = 0; i < 8; i++) {
                unsigned long long ap = f2pack(av[i], av[i]);
                f2fma(accP[i][0], ap, bp0);
                f2fma(accP[i][1], ap, bp1);
                f2fma(accP[i][2], ap, bp2);
                f2fma(accP[i][3], ap, bp3);
            }
        }
        __syncthreads();
    }

    bool fuse = jobA && bx == 0 && mb == 0 && (kb + 1 < NKB);

#pragma unroll
    for (int i = 0; i < 8; i++) {
        int m = row0 + ty * 8 + i;
        if (m >= M) continue;
#pragma unroll
        for (int j2 = 0; j2 < 4; j2 += 2) {
            int n = col0 + tx * 8 + j2 * 2;
            if (n >= N) continue;
            float u0, u1, u2, u3;
            f2unpack(accP[i][j2 + 0], u0, u1);
            f2unpack(accP[i][j2 + 1], u2, u3);
            float* p = Cop + (size_t)m * ldc + n;
            float4 o = *(const float4*)p;
            o.x -= u0; o.y -= u1; o.z -= u2; o.w -= u3;
            *(float4*)p = o;
            if (fuse && m < 64 && n < 64) {
                pool[m * 65 + n + 0] = o.x;
                pool[m * 65 + n + 1] = o.y;
                pool[m * 65 + n + 2] = o.z;
                pool[m * 65 + n + 3] = o.w;
            }
        }
    }

    if (fuse) {
        float* s  = pool;          // [64][65]
        float* vi = pool + 4224;   // [64][65]
        float* sd = pool + 8384;   // [64]
        int r = tid & 63, q = tid >> 6;
        for (int p = tid; p < 64 * 64; p += 256)
            vi[(p >> 6) * 65 + (p & 63)] = ((p >> 6) == (p & 63)) ? 1.0f : 0.0f;
        __syncthreads();
#pragma unroll 1
        for (int j = 0; j < 64; j++) {
            float d = rsqrtf(s[j * 65 + j]);
            if (q == 0 && r > j)  s[r * 65 + j] *= d;
            if (q == 1 && r <= j) vi[j * 65 + r] *= d;
            if (q == 2 && r == j) sd[j] = s[j * 65 + j] * d;
            __syncthreads();
            if (r > j) {
                float sij = s[r * 65 + j];
                for (int t = j + 1 + q; t < 64; t += 4)
                    s[r * 65 + t] -= sij * s[t * 65 + j];
                for (int t = q; t <= j; t += 4)
                    vi[r * 65 + t] -= sij * vi[j * 65 + t];
            }
            __syncthreads();
        }
        int kbn = kb + 1;
        float* Ad = g_A + (size_t)c * NP * NP + (size_t)kbn * 64 * NP + (size_t)kbn * 64;
        float* Li = g_Linv + ((size_t)c * NKB + kbn) * 4096;
        for (int p = tid; p < 64 * 64; p += 256) {
            int rr = p >> 6, qq = p & 63;
            if (qq < rr) Ad[(size_t)rr * NP + qq] = s[rr * 65 + qq];
            else if (qq == rr) Ad[(size_t)rr * NP + qq] = sd[rr];
            Li[p] = vi[rr * 65 + qq];
        }
    }
}

// =====================================================================
// Q split: Q = P^T (K-major), bf16 hi + bf16 residual lo
// =====================================================================
__global__ void k_qsplit()
{
    __shared__ float s[32][33];
    int c = blockIdx.z;
    int k0 = blockIdx.x * 32, j0 = blockIdx.y * 32;
    const float* P = g_B + (size_t)c * NP * NTOT;
    int x = threadIdx.x, y = threadIdx.y;
    for (int yy = y; yy < 32; yy += 8)
        s[yy][x] = P[(size_t)(k0 + yy) * NTOT + j0 + x];
    __syncthreads();
    __nv_bfloat16* Qh = g_Qh + (size_t)c * NTOT * NP;
    __nv_bfloat16* Ql = g_Ql + (size_t)c * NTOT * NP;
    for (int yy = y; yy < 32; yy += 8) {
        float v = s[x][yy];
        __nv_bfloat16 h = __float2bfloat16(v);
        float l = v - __bfloat162float(h);
        Qh[(size_t)(j0 + yy) * NP + k0 + x] = h;
        Ql[(size_t)(j0 + yy) * NP + k0 + x] = __float2bfloat16(l);
    }
}

// =====================================================================
// H GEMM via mma.sync bf16 split: H = Qh Qh^T + Qh Ql^T + Ql Qh^T
// CTA 128x128 tile, 8 warps (4m x 2n), warp tile 32x64.
// Double-buffered cp.async staging (2-deep pipeline).
// Lower tiles + last col tile only.
// =====================================================================
constexpr int QRS = 40;  // smem row stride (bf16 elems)

__global__ __launch_bounds__(256)
void k_hgemm_mma()
{
    int nb = blockIdx.x, mb = blockIdx.y;
    if (nb > mb && nb != (int)gridDim.x - 1) return;
    int c = blockIdx.z;
    const __nv_bfloat16* Qh = g_Qh + (size_t)c * NTOT * NP;
    const __nv_bfloat16* Ql = g_Ql + (size_t)c * NTOT * NP;
    const int row0 = mb * 128, col0 = nb * 128;

    // [buf][array][128*QRS] ; arrays: 0=Ah 1=Bh 2=Al 3=Bl
    __shared__ __align__(16) __nv_bfloat16 sb[2][4][128 * QRS];

    int tid = threadIdx.x;
    int w = tid >> 5, lane = tid & 31;
    int wm = w & 3, wn = w >> 2;

    float acc[2][8][4];
#pragma unroll
    for (int i = 0; i < 2; i++)
#pragma unroll
        for (int j = 0; j < 8; j++)
#pragma unroll
            for (int v = 0; v < 4; v++) acc[i][j][v] = 0.0f;

    const uint32_t lmo = (uint32_t)((lane & 15) * QRS + ((lane >> 4) << 3)) * 2u;

    // per-thread staging coords: 2 iterations x 4 arrays, one int4 each
    int r0 = tid >> 1, ch0 = (tid & 1) << 1;     // rows 0..127, chunks {0,2} then +1
    // each thread copies rows r0, chunks ch0 and ch0+1? Simpler: original scheme:
    // idx = tid + it*256 -> r = idx>>2, ch = idx&3  (512 int4 per array... no, 128*4=512)
    auto stage = [&](int buf, int k0) {
        const __nv_bfloat16* srcs[4] = {
            Qh + (size_t)row0 * NP + k0, Qh + (size_t)col0 * NP + k0,
            Ql + (size_t)row0 * NP + k0, Ql + (size_t)col0 * NP + k0 };
#pragma unroll
        for (int it = 0; it < 2; it++) {
            int idx = tid + it * 256;      // 0..511
            int r = idx >> 2, ch = idx & 3;
#pragma unroll
            for (int arr = 0; arr < 4; arr++) {
                uint32_t dst = smem_u32(&sb[buf][arr][r * QRS + ch * 8]);
                cpa16(dst, srcs[arr] + (size_t)r * NP + ch * 8);
            }
        }
        cpa_commit();
    };

    stage(0, 0);
#pragma unroll 1
    for (int t = 0; t < 32; t++) {
        if (t < 31) stage((t + 1) & 1, (t + 1) * 32);
        if (t < 31) { cpa_wait<1>(); } else { cpa_wait<0>(); }
        __syncthreads();
        int buf = t & 1;
        uint32_t bAh = smem_u32(sb[buf][0]);
        uint32_t bBh = smem_u32(sb[buf][1]);
        uint32_t bAl = smem_u32(sb[buf][2]);
        uint32_t bBl = smem_u32(sb[buf][3]);
#pragma unroll
        for (int ks = 0; ks < 32; ks += 16) {
            uint32_t Ah[2][4], Al[2][4];
#pragma unroll
            for (int mt = 0; mt < 2; mt++) {
                uint32_t off = (uint32_t)((wm * 32 + mt * 16) * QRS + ks) * 2u + lmo;
                ldmx4(Ah[mt], bAh + off);
                ldmx4(Al[mt], bAl + off);
            }
#pragma unroll
            for (int np = 0; np < 4; np++) {
                uint32_t Bh[4], Bl[4];
                uint32_t off = (uint32_t)((wn * 64 + np * 16) * QRS + ks) * 2u + lmo;
                ldmx4(Bh, bBh + off);
                ldmx4(Bl, bBl + off);
#pragma unroll
                for (int sub = 0; sub < 2; sub++) {
                    int nt = np * 2 + sub;
#pragma unroll
                    for (int mt = 0; mt < 2; mt++) {
                        mma16816(acc[mt][nt], Ah[mt], Bh[sub], Bh[sub + 2]);
                        mma16816(acc[mt][nt], Ah[mt], Bl[sub], Bl[sub + 2]);
                        mma16816(acc[mt][nt], Al[mt], Bh[sub], Bh[sub + 2]);
                    }
                }
            }
        }
        __syncthreads();
    }

    float* H = g_H + (size_t)c * NP * NTOT;
    int gr = lane >> 2, gc = (lane & 3) << 1;
#pragma unroll
    for (int mt = 0; mt < 2; mt++) {
        int m = row0 + wm * 32 + mt * 16 + gr;
#pragma unroll
        for (int nt = 0; nt < 8; nt++) {
            int n = col0 + wn * 64 + nt * 8 + gc;
            *(float2*)(H + (size_t)m * NTOT + n)       = make_float2(acc[mt][nt][0], acc[mt][nt][1]);
            *(float2*)(H + (size_t)(m + 8) * NTOT + n) = make_float2(acc[mt][nt][2], acc[mt][nt][3]);
        }
    }
}

// =====================================================================
// Symmetrize H: copy lower triangle -> upper (cols < 1024 only)
// =====================================================================
__global__ void k_symH()
{
    int tc = blockIdx.x, tr = blockIdx.y;
    if (tc < tr) return;
    int c = blockIdx.z;
    float* H = g_H + (size_t)c * NP * NTOT;
    __shared__ float s[32][33];
    int x = threadIdx.x, y0 = threadIdx.y;
    for (int yy = y0; yy < 32; yy += 8)
        s[yy][x] = H[(size_t)(tc * 32 + yy) * NTOT + tr * 32 + x];
    __syncthreads();
    for (int yy = y0; yy < 32; yy += 8) {
        int i = tr * 32 + yy, j = tc * 32 + x;
        if (j > i) H[(size_t)i * NTOT + j] = s[x][yy];
    }
}

// =====================================================================
// Final outputs
// =====================================================================
__global__ void k_fmean(float* __restrict__ out)
{
    int idx = blockIdx.x * blockDim.x + threadIdx.x;
    if (idx >= 4096) return;
    int b = idx >> 10, j = idx & 1023;
    float v = 0.0f;
#pragma unroll
    for (int c = 0; c < LT; c++)
        v += g_M[c * LT + b] * g_H[(size_t)c * NP * NTOT + (size_t)j * NTOT + 1024];
    out[OFF_FMEAN + idx] = v;
    out[OFF_OUT4 + (size_t)j * LT + b] = v;
}

__global__ void k_output(float* __restrict__ out)
{
    size_t t = (size_t)blockIdx.x * blockDim.x + threadIdx.x;
    if (t >= (size_t)4096 * 1024) return;
    int g = (int)(t & 1023);
    size_t ig = t >> 10;
    int a = (int)(ig >> 10);
    int i = (int)(ig & 1023);
    int b = g >> 8;
    int j0 = (g & 255) << 2;
    float4 cxx = *(const float4*)&g_Cxx[(size_t)i * NP + j0];
    float Tab = g_Tm[a * LT + b];
    float4 acc;
    acc.x = Tab * cxx.x;
    acc.y = Tab * cxx.y;
    acc.z = Tab * cxx.z;
    acc.w = Tab * cxx.w;
#pragma unroll
    for (int c = 0; c < LT; c++) {
        float mm = g_M[c * LT + a] * g_M[c * LT + b];
        float4 h = *(const float4*)&g_H[(size_t)c * NP * NTOT + (size_t)i * NTOT + j0];
        acc.x -= mm * h.x;
        acc.y -= mm * h.y;
        acc.z -= mm * h.z;
        acc.w -= mm * h.w;
    }
    size_t col0 = (size_t)b * 1024 + j0;
    *(float4*)&out[OFF_FVAR + ig * 4096 + col0] = acc;
    float4 nz = make_float4(0.f, 0.f, 0.f, 0.f);
    if (ig >= col0 && ig < col0 + 4) {
        float nv = g_noise[a];
        int jj = (int)(ig - col0);
        if (jj == 0) nz.x = nv;
        else if (jj == 1) nz.y = nv;
        else if (jj == 2) nz.z = nv;
        else nz.w = nv;
    }
    *(float4*)&out[OFF_NOISE + ig * 4096 + col0] = nz;
}

// =====================================================================
// Host side
// =====================================================================
extern "C" void kernel_launch(void* const* d_in, const int* in_sizes, int n_in,
                              void* d_out, int out_size)
{
    const float* X        = (const float*)d_in[0];
    const float* test_X   = (const float*)d_in[1];
    const float* Y        = (const float*)d_in[2];
    const float* lnoise   = (const float*)d_in[3];
    const float* cfac     = (const float*)d_in[4];
    const float* lvar     = (const float*)d_in[5];
    const float* lls      = (const float*)d_in[6];
    int rank = in_sizes[4] / LT;
    float* out = (float*)d_out;

    k_setup<<<1, 32>>>(cfac, lvar, lnoise, rank);
    dim3 rg(64, 64);
    k_rbf<<<rg, 256>>>(X, X, lls, 2);           // A_c = lambda_c*C + I
    k_rbf<<<rg, 256>>>(X, test_X, lls, 1);      // Cx into B_c
    k_rbf<<<rg, 256>>>(test_X, test_X, lls, 0); // Cxx
    k_y<<<(LT * NP * 128 + 255) / 256, 256>>>(Y);

    // ---- batched blocked Cholesky fused with forward solve ----
    k_potf2<<<dim3(1, 1, LT), 256>>>(0);
    for (int kb = 0; kb < NKB; kb++) {
        int rem = NP - 64 * (kb + 1);
        k_combo1<<<dim3((rem >> 6) + (NTOT >> 6), 1, LT), 256>>>(kb, rem);
        if (rem > 0) {
            int tilesA = (rem + 127) >> 7;
            k_combo2<<<dim3(tilesA + (NTOT >> 7), tilesA, LT), 256>>>(kb, rem);
        }
    }

    // ---- Q = P^T in split bf16, then H = Q Q^T on tensor cores ----
    k_qsplit<<<dim3(32, 36, LT), dim3(32, 8)>>>();
    k_hgemm_mma<<<dim3(NTOT / 128, NP / 128, LT), 256>>>();
    k_symH<<<dim3(32, 32, LT), dim3(32, 8)>>>();

    // ---- outputs ----
    k_fmean<<<16, 256>>>(out);
    k_output<<<16384, 256>>>(out);
}

// round 14
// speedup vs baseline: 1.5392x; 1.0107x over previous
#include <cuda_runtime.h>
#include <cuda_bf16.h>
#include <math.h>
#include <stdint.h>

// Problem constants (fixed instance)
constexpr int NP   = 1024;   // N == N_ (train/test points)
constexpr int LT   = 4;      // tasks
constexpr int RNK_MAX = 8;
constexpr int NTOT = 1152;   // RHS width: 1024 Cx cols + 1 ytilde col + pad to 9*128
constexpr int NKB  = 16;     // 1024 / 64 block steps

// Output offsets (fp32 elements)
constexpr size_t OFF_FMEAN = 0;
constexpr size_t OFF_FVAR  = 4096;
constexpr size_t OFF_NOISE = OFF_FVAR + (size_t)4096 * 4096;
constexpr size_t OFF_OUT4  = OFF_NOISE + (size_t)4096 * 4096;

// -------- device scratch (static, no allocation) --------
__device__ float g_A[LT * NP * NP];          // lambda_c*C + I, then Cholesky L (lower)
__device__ float g_B[LT * NP * NTOT];        // RHS -> forward-solved P_c (and w_c in col 1024)
__device__ float g_H[LT * NP * NTOT];        // H_c = P_c^T * P_c  (col 1024 = g_c)
__device__ float g_Cxx[NP * NP];             // rbf(test_X, test_X)
__device__ float g_Linv[LT * NKB * 64 * 64]; // per-step 64x64 diag-block inverses
__device__ __nv_bfloat16 g_Qh[LT * (size_t)NTOT * NP]; // Q = P^T, bf16 hi
__device__ __nv_bfloat16 g_Ql[LT * (size_t)NTOT * NP]; // Q residual, bf16 lo
__device__ float g_lambda[LT];
__device__ float g_R[LT * LT];               // R = U^T Dn^{-1/2}
__device__ float g_M[LT * LT];               // M = R * T
__device__ float g_Tm[LT * LT];              // task_K
__device__ float g_noise[LT];                // exp(log_noise)

// -------- packed fp32x2 helpers --------
__device__ __forceinline__ unsigned long long f2pack(float lo, float hi)
{
    unsigned long long r;
    asm("mov.b64 %0, {%1, %2};" : "=l"(r) : "f"(lo), "f"(hi));
    return r;
}
__device__ __forceinline__ void f2unpack(unsigned long long v, float& lo, float& hi)
{
    asm("mov.b64 {%0, %1}, %2;" : "=f"(lo), "=f"(hi) : "l"(v));
}
__device__ __forceinline__ void f2fma(unsigned long long& d,
                                      unsigned long long a, unsigned long long b)
{
    asm("fma.rn.f32x2 %0, %1, %2, %3;" : "=l"(d) : "l"(a), "l"(b), "l"(d));
}

// -------- mma.sync / ldmatrix / cp.async helpers --------
__device__ __forceinline__ uint32_t smem_u32(const void* p)
{
    uint32_t a;
    asm("{ .reg .u64 t; cvta.to.shared.u64 t, %1; cvt.u32.u64 %0, t; }" : "=r"(a) : "l"(p));
    return a;
}
__device__ __forceinline__ void ldmx4(uint32_t* r, uint32_t addr)
{
    asm volatile("ldmatrix.sync.aligned.m8n8.x4.shared.b16 {%0,%1,%2,%3}, [%4];"
        : "=r"(r[0]), "=r"(r[1]), "=r"(r[2]), "=r"(r[3]) : "r"(addr));
}
__device__ __forceinline__ void mma16816(float* d, const uint32_t* a,
                                         uint32_t b0, uint32_t b1)
{
    asm volatile(
        "mma.sync.aligned.m16n8k16.row.col.f32.bf16.bf16.f32 "
        "{%0,%1,%2,%3}, {%4,%5,%6,%7}, {%8,%9}, {%0,%1,%2,%3};"
        : "+f"(d[0]), "+f"(d[1]), "+f"(d[2]), "+f"(d[3])
        : "r"(a[0]), "r"(a[1]), "r"(a[2]), "r"(a[3]), "r"(b0), "r"(b1));
}
__device__ __forceinline__ void cpa16(uint32_t saddr, const void* gptr)
{
    asm volatile("cp.async.cg.shared.global [%0], [%1], 16;" :: "r"(saddr), "l"(gptr));
}
__device__ __forceinline__ void cpa_commit()
{
    asm volatile("cp.async.commit_group;" ::: "memory");
}
template <int N>
__device__ __forceinline__ void cpa_wait()
{
    asm volatile("cp.async.wait_group %0;" :: "n"(N) : "memory");
}

// =====================================================================
// Small setup: task_K, 4x4 Jacobi eigendecomposition, R, M (fp32, 10 sweeps)
// =====================================================================
__global__ void k_setup(const float* __restrict__ cf,
                        const float* __restrict__ log_var,
                        const float* __restrict__ log_noise,
                        int rank)
{
    if (threadIdx.x != 0) return;
    float T[LT][LT], Tt[LT][LT], U[LT][LT], sv[LT];
#pragma unroll
    for (int a = 0; a < LT; a++) sv[a] = expf(-0.5f * log_noise[a]);
    for (int a = 0; a < LT; a++)
        for (int b = 0; b < LT; b++) {
            float s = 0.0f;
            for (int r = 0; r < rank && r < RNK_MAX; r++)
                s += cf[a * rank + r] * cf[b * rank + r];
            if (a == b) s += expf(log_var[a]);
            T[a][b] = s;
        }
#pragma unroll
    for (int a = 0; a < LT; a++)
#pragma unroll
        for (int b = 0; b < LT; b++) {
            Tt[a][b] = sv[a] * sv[b] * T[a][b];
            U[a][b] = (a == b) ? 1.0f : 0.0f;
        }
#pragma unroll 1
    for (int sweep = 0; sweep < 10; sweep++) {
#pragma unroll
        for (int p = 0; p < LT; p++)
#pragma unroll
            for (int q = p + 1; q < LT; q++) {
                float apq = Tt[p][q];
                if (fabsf(apq) < 1e-30f) continue;
                float tau = (Tt[q][q] - Tt[p][p]) / (2.0f * apq);
                float tt = ((tau >= 0.0f) ? 1.0f : -1.0f) / (fabsf(tau) + sqrtf(1.0f + tau * tau));
                float cc = rsqrtf(1.0f + tt * tt);
                float ss = tt * cc;
#pragma unroll
                for (int k = 0; k < LT; k++) {
                    float akp = Tt[k][p], akq = Tt[k][q];
                    Tt[k][p] = cc * akp - ss * akq;
                    Tt[k][q] = ss * akp + cc * akq;
                }
#pragma unroll
                for (int k = 0; k < LT; k++) {
                    float apk = Tt[p][k], aqk = Tt[q][k];
                    Tt[p][k] = cc * apk - ss * aqk;
                    Tt[q][k] = ss * apk + cc * aqk;
                }
#pragma unroll
                for (int k = 0; k < LT; k++) {
                    float ukp = U[k][p], ukq = U[k][q];
                    U[k][p] = cc * ukp - ss * ukq;
                    U[k][q] = ss * ukp + cc * ukq;
                }
            }
    }
    float R[LT][LT];
#pragma unroll
    for (int c = 0; c < LT; c++) {
        g_lambda[c] = Tt[c][c];
#pragma unroll
        for (int a = 0; a < LT; a++) {
            R[c][a] = U[a][c] * sv[a];
            g_R[c * LT + a] = R[c][a];
        }
    }
#pragma unroll
    for (int c = 0; c < LT; c++)
#pragma unroll
        for (int b = 0; b < LT; b++) {
            float m = 0.0f;
#pragma unroll
            for (int a = 0; a < LT; a++) m += R[c][a] * T[a][b];
            g_M[c * LT + b] = m;
        }
#pragma unroll
    for (int a = 0; a < LT; a++) {
#pragma unroll
        for (int b = 0; b < LT; b++) g_Tm[a * LT + b] = T[a][b];
        g_noise[a] = expf(log_noise[a]);
    }
}

// =====================================================================
// RBF kernels. mode 0: Cxx ; mode 1: Cx into B ; mode 2: A_c
// =====================================================================
__global__ void k_rbf(const float* __restrict__ X1, const float* __restrict__ X2,
                      const float* __restrict__ log_ls, int mode)
{
    __shared__ float xs1[16][8];
    __shared__ float xs2[16][8];
    int tid = threadIdx.x;
    int bx = blockIdx.x, by = blockIdx.y;
    if (tid < 128) {
        xs1[tid >> 3][tid & 7] = X1[(by * 16 + (tid >> 3)) * 8 + (tid & 7)];
    } else {
        int q = tid - 128;
        xs2[q >> 3][q & 7] = X2[(bx * 16 + (q >> 3)) * 8 + (q & 7)];
    }
    __syncthreads();
    int tx = tid & 15, ty = tid >> 4;
    float inv_ls2 = expf(-2.0f * log_ls[0]);
    float d2 = 0.0f;
#pragma unroll
    for (int d = 0; d < 8; d++) {
        float df = xs1[ty][d] - xs2[tx][d];
        d2 += df * df;
    }
    float kv = expf(-0.5f * d2 * inv_ls2);
    int i = by * 16 + ty, j = bx * 16 + tx;
    if (mode == 0) {
        g_Cxx[(size_t)i * NP + j] = kv;
    } else if (mode == 1) {
#pragma unroll
        for (int c = 0; c < LT; c++)
            g_B[(size_t)c * NP * NTOT + (size_t)i * NTOT + j] = kv;
    } else {
        float dg = (i == j) ? 1.0f : 0.0f;
#pragma unroll
        for (int c = 0; c < LT; c++)
            g_A[(size_t)c * NP * NP + (size_t)i * NP + j] = g_lambda[c] * kv + dg;
    }
}

// ytilde into column 1024 of each B_c + zero pad columns, coalesced.
__global__ void k_y(const float* __restrict__ Y)
{
    int idx = blockIdx.x * blockDim.x + threadIdx.x;   // < 4*1024*128
    if (idx >= LT * NP * 128) return;
    int p = idx & 127;
    int i = (idx >> 7) & 1023;
    int c = idx >> 17;
    float v = 0.0f;
    if (p == 0) {
#pragma unroll
        for (int a = 0; a < LT; a++) v += g_R[c * LT + a] * Y[i * LT + a];
    }
    g_B[(size_t)c * NP * NTOT + (size_t)i * NTOT + 1024 + p] = v;
}

// =====================================================================
// potf2 (kb=0 only): factor 64x64 diag block + produce L^{-1}
// =====================================================================
__global__ void k_potf2(int kb)
{
    int c = blockIdx.z;
    float* Ad = g_A + (size_t)c * NP * NP + (size_t)kb * 64 * NP + (size_t)kb * 64;
    float* Li = g_Linv + ((size_t)c * NKB + kb) * 64 * 64;
    __shared__ float s[64][65];
    __shared__ float vi[64][65];
    __shared__ float sdiag[64];
    int tid = threadIdx.x;
    int r = tid & 63, q = tid >> 6;
    for (int p = tid; p < 64 * 64; p += 256) {
        int rr = p >> 6, qq = p & 63;
        s[rr][qq] = Ad[(size_t)rr * NP + qq];
        vi[rr][qq] = (rr == qq) ? 1.0f : 0.0f;
    }
    __syncthreads();
#pragma unroll 1
    for (int j = 0; j < 64; j++) {
        float d = rsqrtf(s[j][j]);
        if (q == 0 && r > j)  s[r][j] *= d;
        if (q == 1 && r <= j) vi[j][r] *= d;
        if (q == 2 && r == j) sdiag[j] = s[j][j] * d;
        __syncthreads();
        if (r > j) {
            float sij = s[r][j];
            for (int t = j + 1 + q; t < 64; t += 4)
                s[r][t] -= sij * s[t][j];
            for (int t = q; t <= j; t += 4)
                vi[r][t] -= sij * vi[j][t];
        }
        __syncthreads();
    }
    for (int p = tid; p < 64 * 64; p += 256) {
        int rr = p >> 6, qq = p & 63;
        if (qq < rr) Ad[(size_t)rr * NP + qq] = s[rr][qq];
        else if (qq == rr) Ad[(size_t)rr * NP + qq] = sdiag[rr];
        Li[p] = vi[rr][qq];
    }
}

// =====================================================================
// combo1 (per kb): panel TRSM tiles + B diag-block solve, one launch.
// Double-buffered smem with register prefetch: 1 barrier per K-chunk.
// =====================================================================
__global__ void k_combo1(int kb, int rem)
{
    __shared__ float pool1[2 * 2176];   // [buf][As 16x68 | Bs 16x68]
    int c = blockIdx.z;
    const float* Li = g_Linv + ((size_t)c * NKB + kb) * 4096;
    int panelTiles = rem >> 6;
    int bx = blockIdx.x;
    int tid = threadIdx.x, tx = tid & 15, ty = tid >> 4;
    unsigned long long accP[4][2];
#pragma unroll
    for (int i = 0; i < 4; i++) { accP[i][0] = 0ull; accP[i][1] = 0ull; }

    const float* Aop; const float* Bop; float* Cop;
    int lda, ldb, ldc; bool tb;
    if (bx < panelTiles) {
        float* panel = g_A + (size_t)c * NP * NP + (size_t)(kb + 1) * 64 * NP + (size_t)kb * 64;
        Aop = panel + (size_t)bx * 64 * NP; lda = NP;
        Bop = Li; ldb = 64; tb = true;
        Cop = (float*)Aop; ldc = NP;
    } else {
        int nb = bx - panelTiles;
        float* Bk = g_B + (size_t)c * NP * NTOT + (size_t)kb * 64 * NTOT;
        Aop = Li; lda = 64; tb = false;
        Bop = Bk + nb * 64; ldb = NTOT;
        Cop = (float*)Bop; ldc = NTOT;
    }

    float ra[4], rb[4];
    int akl = tid & 15, aml = tid >> 4;
    auto ldA = [&](int k0) {
#pragma unroll
        for (int p = 0; p < 4; p++)
            ra[p] = Aop[(size_t)(aml + p * 16) * lda + (k0 + akl)];
    };
    auto stA = [&](float* As) {
#pragma unroll
        for (int p = 0; p < 4; p++)
            As[akl * 68 + aml + p * 16] = ra[p];
    };
    int bnl0 = tid & 63, bkl0 = tid >> 6;      // tb=false coords
    int bkl1 = tid & 15, bnl1 = tid >> 4;      // tb=true coords
    auto ldB = [&](int k0) {
        if (!tb) {
#pragma unroll
            for (int p = 0; p < 4; p++)
                rb[p] = Bop[(size_t)(k0 + bkl0 + p * 4) * ldb + bnl0];
        } else {
#pragma unroll
            for (int p = 0; p < 4; p++)
                rb[p] = Bop[(size_t)(bnl1 + p * 16) * ldb + (k0 + bkl1)];
        }
    };
    auto stB = [&](float* Bs) {
        if (!tb) {
#pragma unroll
            for (int p = 0; p < 4; p++)
                Bs[(bkl0 + p * 4) * 68 + bnl0] = rb[p];
        } else {
#pragma unroll
            for (int p = 0; p < 4; p++)
                Bs[bkl1 * 68 + bnl1 + p * 16] = rb[p];
        }
    };

    ldA(0); ldB(0);
    stA(pool1); stB(pool1 + 1088);
    __syncthreads();
#pragma unroll 1
    for (int t = 0; t < 4; t++) {
        float* cur = pool1 + (t & 1) * 2176;
        if (t < 3) { ldA((t + 1) * 16); ldB((t + 1) * 16); }
        const float* As = cur;
        const float* Bs = cur + 1088;
#pragma unroll
        for (int kk = 0; kk < 16; kk++) {
            float4 av = *(const float4*)&As[kk * 68 + ty * 4];
            float4 bv = *(const float4*)&Bs[kk * 68 + tx * 4];
            unsigned long long bp0 = f2pack(bv.x, bv.y);
            unsigned long long bp1 = f2pack(bv.z, bv.w);
            float a_[4] = {av.x, av.y, av.z, av.w};
#pragma unroll
            for (int i = 0; i < 4; i++) {
                unsigned long long ap = f2pack(a_[i], a_[i]);
                f2fma(accP[i][0], ap, bp0);
                f2fma(accP[i][1], ap, bp1);
            }
        }
        if (t < 3) {
            float* nxt = pool1 + ((t + 1) & 1) * 2176;
            stA(nxt); stB(nxt + 1088);
        }
        __syncthreads();
    }
#pragma unroll
    for (int i = 0; i < 4; i++) {
        float v0, v1, v2, v3;
        f2unpack(accP[i][0], v0, v1);
        f2unpack(accP[i][1], v2, v3);
        float* p = Cop + (size_t)(ty * 4 + i) * ldc + tx * 4;
        p[0] = v0; p[1] = v1; p[2] = v2; p[3] = v3;
    }
}

// =====================================================================
// combo2 (per kb): trailing SYRK (lower tiles) + B off-diag update.
// 128x128 tiles, 8x8 micro via FFMA2. K=64, double-buffered staging
// with register prefetch: 1 barrier per 16-K chunk.
// CTA (0,0,jobA) additionally factors the next 64x64 diag block.
// =====================================================================
__global__ __launch_bounds__(256, 2)
void k_combo2(int kb, int rem)
{
    __shared__ float pool[8448];   // [buf][As 16x132 | Bs 16x132] ; potf2 alias
    int c = blockIdx.z;
    int tilesA = (rem + 127) >> 7;
    int bx = blockIdx.x, mb = blockIdx.y;
    bool jobA = bx < tilesA;
    if (jobA && bx > mb) return;
    const float* panel = g_A + (size_t)c * NP * NP + (size_t)(kb + 1) * 64 * NP + (size_t)kb * 64;
    const float* Aop = panel;
    const int lda = NP;
    const int M = rem;
    const float* Bop; int ldb; bool tb; float* Cop; int ldc; int N; int col0;
    if (jobA) {
        Bop = panel; ldb = NP; tb = true;
        Cop = g_A + (size_t)c * NP * NP + (size_t)(kb + 1) * 64 * NP + (size_t)(kb + 1) * 64;
        ldc = NP; N = rem; col0 = bx * 128;
    } else {
        Bop = g_B + (size_t)c * NP * NTOT + (size_t)kb * 64 * NTOT;
        ldb = NTOT; tb = false;
        Cop = g_B + (size_t)c * NP * NTOT + (size_t)(kb + 1) * 64 * NTOT;
        ldc = NTOT; N = NTOT; col0 = (bx - tilesA) * 128;
    }
    const int row0 = mb * 128;
    int tid = threadIdx.x, tx = tid & 15, ty = tid >> 4;
    unsigned long long accP[8][4];
#pragma unroll
    for (int i = 0; i < 8; i++)
#pragma unroll
        for (int j = 0; j < 4; j++) accP[i][j] = 0ull;

    float4 va[2], vb[2];
    int arr = tid >> 2, ac4 = (tid & 3) << 2;
    auto ldA = [&](int k0) {
#pragma unroll
        for (int h = 0; h < 2; h++) {
            int m = row0 + arr + h * 64;
            if (m >= M) m = M - 1;
            va[h] = *(const float4*)(Aop + (size_t)m * lda + k0 + ac4);
        }
    };
    auto stA = [&](float* Asb) {
#pragma unroll
        for (int h = 0; h < 2; h++) {
            Asb[(ac4 + 0) * 132 + arr + h * 64] = va[h].x;
            Asb[(ac4 + 1) * 132 + arr + h * 64] = va[h].y;
            Asb[(ac4 + 2) * 132 + arr + h * 64] = va[h].z;
            Asb[(ac4 + 3) * 132 + arr + h * 64] = va[h].w;
        }
    };
    int bkk = tid >> 4, bn8 = (tid & 15) << 3;  // tb=false coords
    auto ldB = [&](int k0) {
        if (!tb) {
#pragma unroll
            for (int h = 0; h < 2; h++) {
                int n = col0 + bn8 + h * 4;
                vb[h] = *(const float4*)(Bop + (size_t)(k0 + bkk) * ldb + n);
            }
        } else {
#pragma unroll
            for (int h = 0; h < 2; h++) {
                int n = col0 + arr + h * 64;
                if (n >= N) n = N - 1;
                vb[h] = *(const float4*)(Bop + (size_t)n * ldb + k0 + ac4);
            }
        }
    };
    auto stB = [&](float* Bsb) {
        if (!tb) {
#pragma unroll
            for (int h = 0; h < 2; h++)
                *(float4*)&Bsb[bkk * 132 + bn8 + h * 4] = vb[h];
        } else {
#pragma unroll
            for (int h = 0; h < 2; h++) {
                Bsb[(ac4 + 0) * 132 + arr + h * 64] = vb[h].x;
                Bsb[(ac4 + 1) * 132 + arr + h * 64] = vb[h].y;
                Bsb[(ac4 + 2) * 132 + arr + h * 64] = vb[h].z;
                Bsb[(ac4 + 3) * 132 + arr + h * 64] = vb[h].w;
            }
        }
    };

    ldA(0); ldB(0);
    stA(pool); stB(pool + 2112);
    __syncthreads();
#pragma unroll 1
    for (int t = 0; t < 4; t++) {
        float* cur = pool + (t & 1) * 4224;
        if (t < 3) { ldA((t + 1) * 16); ldB((t + 1) * 16); }
        const float* Asb = cur;
        const float* Bsb = cur + 2112;
#pragma unroll
        for (int kk = 0; kk < 16; kk++) {
            float4 a0 = *(const float4*)&Asb[kk * 132 + ty * 8];
            float4 a1 = *(const float4*)&Asb[kk * 132 + ty * 8 + 4];
            float4 b0 = *(const float4*)&Bsb[kk * 132 + tx * 8];
            float4 b1 = *(const float4*)&Bsb[kk * 132 + tx * 8 + 4];
            unsigned long long bp0 = f2pack(b0.x, b0.y);
            unsigned long long bp1 = f2pack(b0.z, b0.w);
            unsigned long long bp2 = f2pack(b1.x, b1.y);
            unsigned long long bp3 = f2pack(b1.z, b1.w);
            float av[8] = {a0.x, a0.y, a0.z, a0.w, a1.x, a1.y, a1.z, a1.w};
#pragma unroll
            for (int i = 0; i < 8; i++) {
                unsigned long long ap = f2pack(av[i], av[i]);
                f2fma(accP[i][0], ap, bp0);
                f2fma(accP[i][1], ap, bp1);
                f2fma(accP[i][2], ap, bp2);
                f2fma(accP[i][3], ap, bp3);
            }
        }
        if (t < 3) {
            float* nxt = pool + ((t + 1) & 1) * 4224;
            stA(nxt); stB(nxt + 2112);
        }
        __syncthreads();
    }

    bool fuse = jobA && bx == 0 && mb == 0 && (kb + 1 < NKB);

#pragma unroll
    for (int i = 0; i < 8; i++) {
        int m = row0 + ty * 8 + i;
        if (m >= M) continue;
#pragma unroll
        for (int j2 = 0; j2 < 4; j2 += 2) {
            int n = col0 + tx * 8 + j2 * 2;
            if (n >= N) continue;
            float u0, u1, u2, u3;
            f2unpack(accP[i][j2 + 0], u0, u1);
            f2unpack(accP[i][j2 + 1], u2, u3);
            float* p = Cop + (size_t)m * ldc + n;
            float4 o = *(const float4*)p;
            o.x -= u0; o.y -= u1; o.z -= u2; o.w -= u3;
            *(float4*)p = o;
            if (fuse && m < 64 && n < 64) {
                pool[m * 65 + n + 0] = o.x;
                pool[m * 65 + n + 1] = o.y;
                pool[m * 65 + n + 2] = o.z;
                pool[m * 65 + n + 3] = o.w;
            }
        }
    }

    if (fuse) {
        float* s  = pool;          // [64][65]
        float* vi = pool + 4224;   // [64][65]
        float* sd = pool + 8384;   // [64]
        int r = tid & 63, q = tid >> 6;
        for (int p = tid; p < 64 * 64; p += 256)
            vi[(p >> 6) * 65 + (p & 63)] = ((p >> 6) == (p & 63)) ? 1.0f : 0.0f;
        __syncthreads();
#pragma unroll 1
        for (int j = 0; j < 64; j++) {
            float d = rsqrtf(s[j * 65 + j]);
            if (q == 0 && r > j)  s[r * 65 + j] *= d;
            if (q == 1 && r <= j) vi[j * 65 + r] *= d;
            if (q == 2 && r == j) sd[j] = s[j * 65 + j] * d;
            __syncthreads();
            if (r > j) {
                float sij = s[r * 65 + j];
                for (int t = j + 1 + q; t < 64; t += 4)
                    s[r * 65 + t] -= sij * s[t * 65 + j];
                for (int t = q; t <= j; t += 4)
                    vi[r * 65 + t] -= sij * vi[j * 65 + t];
            }
            __syncthreads();
        }
        int kbn = kb + 1;
        float* Ad = g_A + (size_t)c * NP * NP + (size_t)kbn * 64 * NP + (size_t)kbn * 64;
        float* Li = g_Linv + ((size_t)c * NKB + kbn) * 4096;
        for (int p = tid; p < 64 * 64; p += 256) {
            int rr = p >> 6, qq = p & 63;
            if (qq < rr) Ad[(size_t)rr * NP + qq] = s[rr * 65 + qq];
            else if (qq == rr) Ad[(size_t)rr * NP + qq] = sd[rr];
            Li[p] = vi[rr * 65 + qq];
        }
    }
}

// =====================================================================
// Q split: Q = P^T (K-major), bf16 hi + bf16 residual lo
// =====================================================================
__global__ void k_qsplit()
{
    __shared__ float s[32][33];
    int c = blockIdx.z;
    int k0 = blockIdx.x * 32, j0 = blockIdx.y * 32;
    const float* P = g_B + (size_t)c * NP * NTOT;
    int x = threadIdx.x, y = threadIdx.y;
    for (int yy = y; yy < 32; yy += 8)
        s[yy][x] = P[(size_t)(k0 + yy) * NTOT + j0 + x];
    __syncthreads();
    __nv_bfloat16* Qh = g_Qh + (size_t)c * NTOT * NP;
    __nv_bfloat16* Ql = g_Ql + (size_t)c * NTOT * NP;
    for (int yy = y; yy < 32; yy += 8) {
        float v = s[x][yy];
        __nv_bfloat16 h = __float2bfloat16(v);
        float l = v - __bfloat162float(h);
        Qh[(size_t)(j0 + yy) * NP + k0 + x] = h;
        Ql[(size_t)(j0 + yy) * NP + k0 + x] = __float2bfloat16(l);
    }
}

// =====================================================================
// H GEMM via mma.sync bf16 split: H = Qh Qh^T + Qh Ql^T + Ql Qh^T
// CTA 128x128 tile, 8 warps (4m x 2n), warp tile 32x64.
// Double-buffered cp.async staging (2-deep pipeline).
// Lower tiles + last col tile only.
// =====================================================================
constexpr int QRS = 40;  // smem row stride (bf16 elems)

__global__ __launch_bounds__(256)
void k_hgemm_mma()
{
    int nb = blockIdx.x, mb = blockIdx.y;
    if (nb > mb && nb != (int)gridDim.x - 1) return;
    int c = blockIdx.z;
    const __nv_bfloat16* Qh = g_Qh + (size_t)c * NTOT * NP;
    const __nv_bfloat16* Ql = g_Ql + (size_t)c * NTOT * NP;
    const int row0 = mb * 128, col0 = nb * 128;

    __shared__ __align__(16) __nv_bfloat16 sb[2][4][128 * QRS];

    int tid = threadIdx.x;
    int w = tid >> 5, lane = tid & 31;
    int wm = w & 3, wn = w >> 2;

    float acc[2][8][4];
#pragma unroll
    for (int i = 0; i < 2; i++)
#pragma unroll
        for (int j = 0; j < 8; j++)
#pragma unroll
            for (int v = 0; v < 4; v++) acc[i][j][v] = 0.0f;

    const uint32_t lmo = (uint32_t)((lane & 15) * QRS + ((lane >> 4) << 3)) * 2u;

    auto stage = [&](int buf, int k0) {
        const __nv_bfloat16* srcs[4] = {
            Qh + (size_t)row0 * NP + k0, Qh + (size_t)col0 * NP + k0,
            Ql + (size_t)row0 * NP + k0, Ql + (size_t)col0 * NP + k0 };
#pragma unroll
        for (int it = 0; it < 2; it++) {
            int idx = tid + it * 256;      // 0..511
            int r = idx >> 2, ch = idx & 3;
#pragma unroll
            for (int arr = 0; arr < 4; arr++) {
                uint32_t dst = smem_u32(&sb[buf][arr][r * QRS + ch * 8]);
                cpa16(dst, srcs[arr] + (size_t)r * NP + ch * 8);
            }
        }
        cpa_commit();
    };

    stage(0, 0);
#pragma unroll 1
    for (int t = 0; t < 32; t++) {
        if (t < 31) stage((t + 1) & 1, (t + 1) * 32);
        if (t < 31) { cpa_wait<1>(); } else { cpa_wait<0>(); }
        __syncthreads();
        int buf = t & 1;
        uint32_t bAh = smem_u32(sb[buf][0]);
        uint32_t bBh = smem_u32(sb[buf][1]);
        uint32_t bAl = smem_u32(sb[buf][2]);
        uint32_t bBl = smem_u32(sb[buf][3]);
#pragma unroll
        for (int ks = 0; ks < 32; ks += 16) {
            uint32_t Ah[2][4], Al[2][4];
#pragma unroll
            for (int mt = 0; mt < 2; mt++) {
                uint32_t off = (uint32_t)((wm * 32 + mt * 16) * QRS + ks) * 2u + lmo;
                ldmx4(Ah[mt], bAh + off);
                ldmx4(Al[mt], bAl + off);
            }
#pragma unroll
            for (int np = 0; np < 4; np++) {
                uint32_t Bh[4], Bl[4];
                uint32_t off = (uint32_t)((wn * 64 + np * 16) * QRS + ks) * 2u + lmo;
                ldmx4(Bh, bBh + off);
                ldmx4(Bl, bBl + off);
#pragma unroll
                for (int sub = 0; sub < 2; sub++) {
                    int nt = np * 2 + sub;
#pragma unroll
                    for (int mt = 0; mt < 2; mt++) {
                        mma16816(acc[mt][nt], Ah[mt], Bh[sub], Bh[sub + 2]);
                        mma16816(acc[mt][nt], Ah[mt], Bl[sub], Bl[sub + 2]);
                        mma16816(acc[mt][nt], Al[mt], Bh[sub], Bh[sub + 2]);
                    }
                }
            }
        }
        __syncthreads();
    }

    float* H = g_H + (size_t)c * NP * NTOT;
    int gr = lane >> 2, gc = (lane & 3) << 1;
#pragma unroll
    for (int mt = 0; mt < 2; mt++) {
        int m = row0 + wm * 32 + mt * 16 + gr;
#pragma unroll
        for (int nt = 0; nt < 8; nt++) {
            int n = col0 + wn * 64 + nt * 8 + gc;
            *(float2*)(H + (size_t)m * NTOT + n)       = make_float2(acc[mt][nt][0], acc[mt][nt][1]);
            *(float2*)(H + (size_t)(m + 8) * NTOT + n) = make_float2(acc[mt][nt][2], acc[mt][nt][3]);
        }
    }
}

// =====================================================================
// Symmetrize H: copy lower triangle -> upper (cols < 1024 only)
// =====================================================================
__global__ void k_symH()
{
    int tc = blockIdx.x, tr = blockIdx.y;
    if (tc < tr) return;
    int c = blockIdx.z;
    float* H = g_H + (size_t)c * NP * NTOT;
    __shared__ float s[32][33];
    int x = threadIdx.x, y0 = threadIdx.y;
    for (int yy = y0; yy < 32; yy += 8)
        s[yy][x] = H[(size_t)(tc * 32 + yy) * NTOT + tr * 32 + x];
    __syncthreads();
    for (int yy = y0; yy < 32; yy += 8) {
        int i = tr * 32 + yy, j = tc * 32 + x;
        if (j > i) H[(size_t)i * NTOT + j] = s[x][yy];
    }
}

// =====================================================================
// Final outputs
// =====================================================================
__global__ void k_fmean(float* __restrict__ out)
{
    int idx = blockIdx.x * blockDim.x + threadIdx.x;
    if (idx >= 4096) return;
    int b = idx >> 10, j = idx & 1023;
    float v = 0.0f;
#pragma unroll
    for (int c = 0; c < LT; c++)
        v += g_M[c * LT + b] * g_H[(size_t)c * NP * NTOT + (size_t)j * NTOT + 1024];
    out[OFF_FMEAN + idx] = v;
    out[OFF_OUT4 + (size_t)j * LT + b] = v;
}

__global__ void k_output(float* __restrict__ out)
{
    size_t t = (size_t)blockIdx.x * blockDim.x + threadIdx.x;
    if (t >= (size_t)4096 * 1024) return;
    int g = (int)(t & 1023);
    size_t ig = t >> 10;
    int a = (int)(ig >> 10);
    int i = (int)(ig & 1023);
    int b = g >> 8;
    int j0 = (g & 255) << 2;
    float4 cxx = *(const float4*)&g_Cxx[(size_t)i * NP + j0];
    float Tab = g_Tm[a * LT + b];
    float4 acc;
    acc.x = Tab * cxx.x;
    acc.y = Tab * cxx.y;
    acc.z = Tab * cxx.z;
    acc.w = Tab * cxx.w;
#pragma unroll
    for (int c = 0; c < LT; c++) {
        float mm = g_M[c * LT + a] * g_M[c * LT + b];
        float4 h = *(const float4*)&g_H[(size_t)c * NP * NTOT + (size_t)i * NTOT + j0];
        acc.x -= mm * h.x;
        acc.y -= mm * h.y;
        acc.z -= mm * h.z;
        acc.w -= mm * h.w;
    }
    size_t col0 = (size_t)b * 1024 + j0;
    *(float4*)&out[OFF_FVAR + ig * 4096 + col0] = acc;
    float4 nz = make_float4(0.f, 0.f, 0.f, 0.f);
    if (ig >= col0 && ig < col0 + 4) {
        float nv = g_noise[a];
        int jj = (int)(ig - col0);
        if (jj == 0) nz.x = nv;
        else if (jj == 1) nz.y = nv;
        else if (jj == 2) nz.z = nv;
        else nz.w = nv;
    }
    *(float4*)&out[OFF_NOISE + ig * 4096 + col0] = nz;
}

// =====================================================================
// Host side
// =====================================================================
extern "C" void kernel_launch(void* const* d_in, const int* in_sizes, int n_in,
                              void* d_out, int out_size)
{
    const float* X        = (const float*)d_in[0];
    const float* test_X   = (const float*)d_in[1];
    const float* Y        = (const float*)d_in[2];
    const float* lnoise   = (const float*)d_in[3];
    const float* cfac     = (const float*)d_in[4];
    const float* lvar     = (const float*)d_in[5];
    const float* lls      = (const float*)d_in[6];
    int rank = in_sizes[4] / LT;
    float* out = (float*)d_out;

    k_setup<<<1, 32>>>(cfac, lvar, lnoise, rank);
    dim3 rg(64, 64);
    k_rbf<<<rg, 256>>>(X, X, lls, 2);           // A_c = lambda_c*C + I
    k_rbf<<<rg, 256>>>(X, test_X, lls, 1);      // Cx into B_c
    k_rbf<<<rg, 256>>>(test_X, test_X, lls, 0); // Cxx
    k_y<<<(LT * NP * 128 + 255) / 256, 256>>>(Y);

    // ---- batched blocked Cholesky fused with forward solve ----
    k_potf2<<<dim3(1, 1, LT), 256>>>(0);
    for (int kb = 0; kb < NKB; kb++) {
        int rem = NP - 64 * (kb + 1);
        k_combo1<<<dim3((rem >> 6) + (NTOT >> 6), 1, LT), 256>>>(kb, rem);
        if (rem > 0) {
            int tilesA = (rem + 127) >> 7;
            k_combo2<<<dim3(tilesA + (NTOT >> 7), tilesA, LT), 256>>>(kb, rem);
        }
    }

    // ---- Q = P^T in split bf16, then H = Q Q^T on tensor cores ----
    k_qsplit<<<dim3(32, 36, LT), dim3(32, 8)>>>();
    k_hgemm_mma<<<dim3(NTOT / 128, NP / 128, LT), 256>>>();
    k_symH<<<dim3(32, 32, LT), dim3(32, 8)>>>();

    // ---- outputs ----
    k_fmean<<<16, 256>>>(out);
    k_output<<<16384, 256>>>(out);
}